// round 11
// baseline (speedup 1.0000x reference)
#include <cuda_runtime.h>
#include <cuda_fp16.h>
#include <math.h>
#include <stdint.h>

// ---------------- problem constants (from setup_inputs, deterministic) ----------
#define LXX     2048
#define LCC     4096
#define DM      1024
#define NH      16
#define HDIM    64
#define HID     2816
#define LTOT    6144
#define LOUT    4096
#define POS_X   4096
#define POS_C   0
#define HWSP    2048
#define MAXPOS  6144

#define WSCALE     64.0f
#define WSCALE_INV 0.015625f
#define QSCALE     0.125f

// ---------------- scratch (device globals; no runtime allocation) ---------------
__device__ float  g_attn  [LXX * DM];          // a1 fp32 staging
__device__ float  g_h1    [LOUT * DM];
__device__ float  g_cos   [MAXPOS * 32];
__device__ float  g_sin   [MAXPOS * 32];

__device__ __half g_qkv_h [LTOT * 3 * DM];     // QKV projection, fp16
__device__ __half g_gateup[LOUT * 2 * HID];    // FFN1 output, fp16
__device__ __half g_act_h [LOUT * HID];        // A operand of weight GEMMs

// single fp16 weights [N][K], pre-scaled by WSCALE
__device__ __half g_wqkv[3 * DM * DM];
__device__ __half g_wout[DM * DM];
__device__ __half g_w13 [2 * HID * DM];
__device__ __half g_w2  [DM * HID];

// fp16 attention operands (Q pre-scaled by QSCALE)
__device__ __half g_qx[LXX * DM];
__device__ __half g_qs[2048 * DM];
__device__ __half g_kx[LXX * DM];
__device__ __half g_kc[LCC * DM];

// ---------------- helpers (portable: sm_80+ PTX) ----------------------------------
__device__ __forceinline__ uint32_t smem_to_u32(const void* p) {
    uint32_t a;
    asm("{ .reg .u64 t; cvta.to.shared.u64 t, %1; cvt.u32.u64 %0, t; }" : "=r"(a) : "l"(p));
    return a;
}
#define SMEM_SWIZZLE_128B(b) ((b) ^ (((b) >> 3) & 0x70))

__device__ __forceinline__ void cp16(uint32_t s, const void* g) {
    asm volatile("cp.async.cg.shared.global [%0], [%1], 16;" :: "r"(s), "l"(g) : "memory");
}
__device__ __forceinline__ void cp_commit() {
    asm volatile("cp.async.commit_group;" ::: "memory");
}
template<int N> __device__ __forceinline__ void cp_wait() {
    asm volatile("cp.async.wait_group %0;" :: "n"(N) : "memory");
}

__device__ __forceinline__ void ldsm_x4(uint32_t* r, uint32_t addr) {
    asm volatile("ldmatrix.sync.aligned.m8n8.x4.shared.b16 {%0,%1,%2,%3}, [%4];"
        : "=r"(r[0]), "=r"(r[1]), "=r"(r[2]), "=r"(r[3]) : "r"(addr));
}
__device__ __forceinline__ void ldsm_x4_t(uint32_t* r, uint32_t addr) {
    asm volatile("ldmatrix.sync.aligned.m8n8.x4.trans.shared.b16 {%0,%1,%2,%3}, [%4];"
        : "=r"(r[0]), "=r"(r[1]), "=r"(r[2]), "=r"(r[3]) : "r"(addr));
}
__device__ __forceinline__ void mma_f16(float* c, const uint32_t* a, const uint32_t* b) {
    asm volatile("mma.sync.aligned.m16n8k16.row.col.f32.f16.f16.f32 "
        "{%0,%1,%2,%3}, {%4,%5,%6,%7}, {%8,%9}, {%0,%1,%2,%3};"
        : "+f"(c[0]), "+f"(c[1]), "+f"(c[2]), "+f"(c[3])
        : "r"(a[0]), "r"(a[1]), "r"(a[2]), "r"(a[3]), "r"(b[0]), "r"(b[1]));
}

// fast exp on FMA pipe (x <= 0), rel err ~2e-6
__device__ __forceinline__ float fexp(float x) {
    x = fmaxf(x, -87.0f);
    float t = x * 1.4426950408889634f;
    float r = t + 12582912.0f;
    float n = r - 12582912.0f;
    float f = t - n;
    float p = 0.0013298820f;
    p = fmaf(p, f, 0.0096181291f);
    p = fmaf(p, f, 0.0555041087f);
    p = fmaf(p, f, 0.2402265069f);
    p = fmaf(p, f, 0.6931471806f);
    p = fmaf(p, f, 1.0f);
    int ni = (int)n;
    return p * __int_as_float((ni + 127) << 23);
}

// ---------------- rope cos/sin table (fp64 angles) -------------------------------
__global__ void build_rope_table() {
    int idx = blockIdx.x * blockDim.x + threadIdx.x;
    if (idx >= MAXPOS * 32) return;
    int pos = idx >> 5, j = idx & 31;
    double inv = pow(10000.0, -((double)(2 * j)) / 64.0);
    double ang = (double)pos * inv;
    g_cos[idx] = (float)cos(ang);
    g_sin[idx] = (float)sin(ang);
}

// ---------------- LayerNorm fused with fp16 output ---------------------------------
__global__ void ln_f16_kernel(const float* __restrict__ in,
                              __half* __restrict__ out,
                              const float* __restrict__ gam,
                              const float* __restrict__ bet) {
    __shared__ float sh[32];
    __shared__ float s_mean, s_rstd;
    int row = blockIdx.x, t = threadIdx.x;
    const float* x = in + (size_t)row * DM;
    float v[4];
    float s = 0.f;
#pragma unroll
    for (int i = 0; i < 4; i++) { v[i] = x[t + 256 * i]; s += v[i]; }
#pragma unroll
    for (int o = 16; o; o >>= 1) s += __shfl_xor_sync(0xffffffffu, s, o);
    if ((t & 31) == 0) sh[t >> 5] = s;
    __syncthreads();
    if (t < 32) {
        float z = (t < 8) ? sh[t] : 0.f;
#pragma unroll
        for (int o = 4; o; o >>= 1) z += __shfl_xor_sync(0xffffffffu, z, o);
        if (t == 0) s_mean = z * (1.f / 1024.f);
    }
    __syncthreads();
    float mean = s_mean;
    float q = 0.f;
#pragma unroll
    for (int i = 0; i < 4; i++) { float d = v[i] - mean; q += d * d; }
#pragma unroll
    for (int o = 16; o; o >>= 1) q += __shfl_xor_sync(0xffffffffu, q, o);
    if ((t & 31) == 0) sh[t >> 5] = q;
    __syncthreads();
    if (t < 32) {
        float z = (t < 8) ? sh[t] : 0.f;
#pragma unroll
        for (int o = 4; o; o >>= 1) z += __shfl_xor_sync(0xffffffffu, z, o);
        if (t == 0) s_rstd = rsqrtf(z * (1.f / 1024.f) + 1e-5f);
    }
    __syncthreads();
    float rstd = s_rstd;
#pragma unroll
    for (int i = 0; i < 4; i++) {
        int c = t + 256 * i;
        float r = (v[i] - mean) * rstd * gam[c] + bet[c];
        out[(size_t)row * DM + c] = __float2half(r);
    }
}

// ---------------- RoPE: fp16 strided in -> fp16 contiguous out ---------------------
__global__ void rope_f16_kernel(const __half* __restrict__ src, int lds,
                                __half* __restrict__ out,
                                int L, int pos0, float scale) {
    int idx = blockIdx.x * blockDim.x + threadIdx.x;
    if (idx >= L * 512) return;
    int j = idx & 31, h = (idx >> 5) & 15, l = idx >> 9;
    int pos = pos0 + l;
    float c = g_cos[pos * 32 + j], s = g_sin[pos * 32 + j];
    const __half* p = src + (size_t)l * lds + h * HDIM;
    float t1 = __half2float(p[j]), t2 = __half2float(p[j + 32]);
    size_t o = (size_t)l * DM + h * HDIM;
    out[o + j]      = __float2half((t1 * c - t2 * s) * scale);
    out[o + j + 32] = __float2half((t2 * c + t1 * s) * scale);
}

// ---------------- weight transpose + single fp16 (pre-scaled by WSCALE) ------------
__global__ void wt_f16_kernel(const float* __restrict__ w,
                              __half* __restrict__ o, int K, int N) {
    __shared__ float t[32][33];
    int n0 = blockIdx.x * 32, k0 = blockIdx.y * 32;
    int tx = threadIdx.x, ty = threadIdx.y;
#pragma unroll
    for (int i = 0; i < 32; i += 8)
        t[ty + i][tx] = w[(size_t)(k0 + ty + i) * N + n0 + tx];
    __syncthreads();
#pragma unroll
    for (int i = 0; i < 32; i += 8) {
        int n = n0 + ty + i, k = k0 + tx;
        o[(size_t)n * K + k] = __float2half(t[tx][ty + i] * WSCALE);
    }
}

// ---------------- silu(g)*u (fp16 in) fused with fp16 output ------------------------
__global__ void silu_mul_f16_kernel(const __half* __restrict__ gu,
                                    __half* __restrict__ out) {
    int col = blockIdx.x * 256 + threadIdx.x;
    int row = blockIdx.y;
    float g = __half2float(gu[(size_t)row * (2 * HID) + col]);
    float u = __half2float(gu[(size_t)row * (2 * HID) + HID + col]);
    float r = (g / (1.f + __expf(-g))) * u;
    out[(size_t)row * HID + col] = __float2half(r);
}

// ---------------- fp16 single-pass GEMM, cp.async 3-stage pipeline ------------------
// C = (1/WSCALE) * A[M][K] * B[N][K]^T (+bias). Out fp32 (+residual) or fp16 (Ch).
static const int GEMM_SMEM = 3 * 2 * 16384;   // 98304

__global__ void __launch_bounds__(256, 2)
mma_gemm_kernel(const __half* __restrict__ A, const __half* __restrict__ B,
                float* __restrict__ C, __half* __restrict__ Ch,
                const float* __restrict__ bias,
                const float* __restrict__ res0, const float* __restrict__ res1, int split,
                int M, int N, int K) {
    extern __shared__ char smem[];
    uint32_t sbase = smem_to_u32(smem);

    int tid = threadIdx.x;
    int wid = tid >> 5, lane = tid & 31;
    int wr = wid >> 2, wc = wid & 3;
    int m0 = blockIdx.y * 128, n0 = blockIdx.x * 128;

    int lr  = lane & 7;
    int lq  = lane >> 3;
    int qlo = lq & 1, qhi = lq >> 1;

    uint32_t aoff[4];
#pragma unroll
    for (int mt = 0; mt < 4; mt++) {
        int row = wr * 64 + mt * 16 + qlo * 8 + lr;
        aoff[mt] = (uint32_t)(row * 128) + (uint32_t)((qhi * 16) ^ ((row & 7) * 16));
    }
    uint32_t boff[2];
#pragma unroll
    for (int np = 0; np < 2; np++) {
        int row = wc * 32 + np * 16 + qhi * 8 + lr;
        boff[np] = (uint32_t)(row * 128) + (uint32_t)((qlo * 16) ^ ((row & 7) * 16));
    }

    auto issue = [&](int st, int kc0) {
        uint32_t base = sbase + (uint32_t)st * 32768;
#pragma unroll
        for (int it = 0; it < 4; it++) {
            int idx = tid + it * 256;
            int r = idx >> 3, q = idx & 7;
            uint32_t so = SMEM_SWIZZLE_128B((uint32_t)(r * 128 + q * 16));
            cp16(base + so,         A + (size_t)(m0 + r) * K + kc0 + q * 8);
            cp16(base + 16384 + so, B + (size_t)(n0 + r) * K + kc0 + q * 8);
        }
        cp_commit();
    };

    float acc[4][4][4] = {};
    int nchunks = K >> 6;

    issue(0, 0);
    if (nchunks > 1) issue(1, 64);
    int st = 0;
    for (int kc = 0; kc < nchunks; kc++) {
        if (kc + 1 < nchunks) cp_wait<1>(); else cp_wait<0>();
        __syncthreads();
        if (kc + 2 < nchunks) {
            int st2 = st + 2; if (st2 >= 3) st2 -= 3;
            issue(st2, (kc + 2) << 6);
        }

        uint32_t sA = sbase + (uint32_t)st * 32768;
        uint32_t sB = sA + 16384;

#pragma unroll
        for (int ks = 0; ks < 4; ks++) {
            uint32_t kx = (uint32_t)(ks << 5);
            uint32_t bh[2][4];
#pragma unroll
            for (int np = 0; np < 2; np++)
                ldsm_x4(bh[np], sB + (boff[np] ^ kx));
#pragma unroll
            for (int mt = 0; mt < 4; mt++) {
                uint32_t ah[4];
                ldsm_x4(ah, sA + (aoff[mt] ^ kx));
#pragma unroll
                for (int nt = 0; nt < 4; nt++)
                    mma_f16(acc[mt][nt], ah, &bh[nt >> 1][(nt & 1) * 2]);
            }
        }
        if (++st >= 3) st -= 3;
    }

    int g = lane >> 2, tg = lane & 3;
#pragma unroll
    for (int mt = 0; mt < 4; mt++) {
#pragma unroll
        for (int half = 0; half < 2; half++) {
            int row = m0 + wr * 64 + mt * 16 + g + half * 8;
            const float* rp = nullptr;
            if (res0) rp = ((row < split) ? res0 : res1) + (size_t)row * N;
#pragma unroll
            for (int nt = 0; nt < 4; nt++) {
                int col = n0 + wc * 32 + nt * 8 + tg * 2;
                float vx = acc[mt][nt][half * 2 + 0] * WSCALE_INV;
                float vy = acc[mt][nt][half * 2 + 1] * WSCALE_INV;
                if (bias) { vx += bias[col]; vy += bias[col + 1]; }
                if (Ch) {
                    *(__half2*)(Ch + (size_t)row * N + col) = __floats2half2_rn(vx, vy);
                } else {
                    if (rp) { vx += rp[col]; vy += rp[col + 1]; }
                    *(float2*)(C + (size_t)row * N + col) = make_float2(vx, vy);
                }
            }
        }
    }
}

// ---------------- fp16 flash attention, BQ=64, cp.async 3-stage ---------------------
// Q single fp16 (pre-scaled QSCALE), K single fp16, V single fp16 (strided ldv).
// mode 0: write fp32 O; 1: read fp32 O, add, write fp16; 2: write fp16.
static const int ATTN_SMEM = 3 * 2 * 8192;    // 49152

__global__ void __launch_bounds__(128)
attn_mma(const __half* __restrict__ Q, const __half* __restrict__ K,
         const __half* __restrict__ V, int ldv,
         float* __restrict__ O, __half* __restrict__ Oh,
         int LK, int causal, int mode) {
    extern __shared__ char smema[];
    uint32_t sb = smem_to_u32(smema);

    int tid = threadIdx.x;
    int wid = tid >> 5, lane = tid & 31;
    int g = lane >> 2, tg = lane & 3;
    int lr = lane & 7, qlo = (lane >> 3) & 1, qhi = lane >> 4;
    int q0 = blockIdx.x * 64;
    int h  = blockIdx.y;

    // ---- stage Q (into stage-0 region), extract fragments ----
#pragma unroll
    for (int it = 0; it < 4; it++) {
        int e = tid + it * 128;           // 0..511
        int row = e >> 3, q = e & 7;
        uint32_t off = (uint32_t)(row * 128) + (uint32_t)((q * 16) ^ ((row & 7) * 16));
        *(uint4*)(smema + off) = *(const uint4*)(Q + (size_t)(q0 + row) * DM + h * HDIM + q * 8);
    }
    __syncthreads();
    uint32_t qf[4][4];
    {
        int arow = wid * 16 + qlo * 8 + lr;
        uint32_t abase = (uint32_t)(arow * 128) + (uint32_t)((qhi * 16) ^ ((arow & 7) * 16));
#pragma unroll
        for (int ks = 0; ks < 4; ks++)
            ldsm_x4(qf[ks], sb + (abase ^ (uint32_t)(ks << 5)));
    }
    __syncthreads();

    auto issue = [&](int st, int k0) {
        uint32_t base = sb + (uint32_t)st * 16384;
#pragma unroll
        for (int it = 0; it < 4; it++) {
            int e = tid + it * 128;
            int row = e >> 3, q = e & 7;
            uint32_t off = (uint32_t)(row * 128) + (uint32_t)((q * 16) ^ ((row & 7) * 16));
            cp16(base + off,        K + (size_t)(k0 + row) * DM + h * HDIM + q * 8);
            cp16(base + 8192 + off, V + (size_t)(k0 + row) * ldv + h * HDIM + q * 8);
        }
        cp_commit();
    };

    float o[8][4] = {};
    float m0r = -1e30f, m1r = -1e30f, l0r = 0.f, l1r = 0.f;

    int ntiles = causal ? ((int)blockIdx.x + 1) : (LK >> 6);
    issue(0, 0);
    if (ntiles > 1) issue(1, 64);
    int st = 0;
    for (int kt = 0; kt < ntiles; kt++) {
        int k0 = kt << 6;
        if (kt + 1 < ntiles) cp_wait<1>(); else cp_wait<0>();
        __syncthreads();
        if (kt + 2 < ntiles) {
            int st2 = st + 2; if (st2 >= 3) st2 -= 3;
            issue(st2, (kt + 2) << 6);
        }

        uint32_t sK = sb + (uint32_t)st * 16384;
        uint32_t sV = sK + 8192;

        // ---- S = Q K^T (single pass) ----
        float s[8][4] = {};
#pragma unroll
        for (int ks = 0; ks < 4; ks++) {
            uint32_t kx = (uint32_t)(ks << 5);
            uint32_t bf[4][4];
#pragma unroll
            for (int np = 0; np < 4; np++) {
                int br = np * 16 + qhi * 8 + lr;
                uint32_t boff = (uint32_t)(br * 128) +
                                (uint32_t)(((qlo * 16) ^ (int)kx) ^ ((br & 7) * 16));
                ldsm_x4(bf[np], sK + boff);
            }
#pragma unroll
            for (int nt = 0; nt < 8; nt++)
                mma_f16(s[nt], qf[ks], &bf[nt >> 1][(nt & 1) * 2]);
        }

        // ---- causal mask (diagonal tile only) ----
        if (causal && kt == (int)blockIdx.x) {
            int r0 = q0 + wid * 16 + g, r1 = r0 + 8;
#pragma unroll
            for (int nt = 0; nt < 8; nt++) {
                int kbase = k0 + nt * 8 + tg * 2;
                if (kbase > r0)     s[nt][0] = -1e30f;
                if (kbase + 1 > r0) s[nt][1] = -1e30f;
                if (kbase > r1)     s[nt][2] = -1e30f;
                if (kbase + 1 > r1) s[nt][3] = -1e30f;
            }
        }

        // ---- online softmax ----
        float mx0 = -1e30f, mx1 = -1e30f;
#pragma unroll
        for (int nt = 0; nt < 8; nt++) {
            mx0 = fmaxf(mx0, fmaxf(s[nt][0], s[nt][1]));
            mx1 = fmaxf(mx1, fmaxf(s[nt][2], s[nt][3]));
        }
        mx0 = fmaxf(mx0, __shfl_xor_sync(0xffffffffu, mx0, 1));
        mx0 = fmaxf(mx0, __shfl_xor_sync(0xffffffffu, mx0, 2));
        mx1 = fmaxf(mx1, __shfl_xor_sync(0xffffffffu, mx1, 1));
        mx1 = fmaxf(mx1, __shfl_xor_sync(0xffffffffu, mx1, 2));
        float mn0 = fmaxf(m0r, mx0), mn1 = fmaxf(m1r, mx1);
        float al0 = fexp(m0r - mn0), al1 = fexp(m1r - mn1);
        float sum0 = 0.f, sum1 = 0.f;
#pragma unroll
        for (int nt = 0; nt < 8; nt++) {
            s[nt][0] = fexp(s[nt][0] - mn0);
            s[nt][1] = fexp(s[nt][1] - mn0);
            s[nt][2] = fexp(s[nt][2] - mn1);
            s[nt][3] = fexp(s[nt][3] - mn1);
            sum0 += s[nt][0] + s[nt][1];
            sum1 += s[nt][2] + s[nt][3];
        }
        sum0 += __shfl_xor_sync(0xffffffffu, sum0, 1);
        sum0 += __shfl_xor_sync(0xffffffffu, sum0, 2);
        sum1 += __shfl_xor_sync(0xffffffffu, sum1, 1);
        sum1 += __shfl_xor_sync(0xffffffffu, sum1, 2);
        l0r = l0r * al0 + sum0; m0r = mn0;
        l1r = l1r * al1 + sum1; m1r = mn1;
#pragma unroll
        for (int nt = 0; nt < 8; nt++) {
            o[nt][0] *= al0; o[nt][1] *= al0;
            o[nt][2] *= al1; o[nt][3] *= al1;
        }

        // ---- O += P V (single pass), V via ldmatrix.trans ----
#pragma unroll
        for (int kb = 0; kb < 4; kb++) {
            uint32_t ph[4];
            {
                __half2 p0 = __floats2half2_rn(s[2 * kb][0],     s[2 * kb][1]);
                __half2 p1 = __floats2half2_rn(s[2 * kb][2],     s[2 * kb][3]);
                __half2 p2 = __floats2half2_rn(s[2 * kb + 1][0], s[2 * kb + 1][1]);
                __half2 p3 = __floats2half2_rn(s[2 * kb + 1][2], s[2 * kb + 1][3]);
                ph[0] = *(uint32_t*)&p0; ph[1] = *(uint32_t*)&p1;
                ph[2] = *(uint32_t*)&p2; ph[3] = *(uint32_t*)&p3;
            }
            uint32_t vf[4][4];
            int vr = kb * 16 + qlo * 8 + lr;
            uint32_t vrow = (uint32_t)(vr * 128);
            uint32_t vsw  = (uint32_t)((vr & 7) * 16);
#pragma unroll
            for (int np = 0; np < 4; np++)
                ldsm_x4_t(vf[np], sV + vrow + (((uint32_t)(np * 32 + qhi * 16)) ^ vsw));
#pragma unroll
            for (int nt = 0; nt < 8; nt++)
                mma_f16(o[nt], ph, &vf[nt >> 1][(nt & 1) * 2]);
        }
        if (++st >= 3) st -= 3;
    }

    // ---- epilogue ----
    float inv0 = 1.f / l0r, inv1 = 1.f / l1r;
    int row0 = q0 + wid * 16 + g;
    int row1 = row0 + 8;
#pragma unroll
    for (int nt = 0; nt < 8; nt++) {
        int col = h * HDIM + nt * 8 + tg * 2;
        float v00 = o[nt][0] * inv0, v01 = o[nt][1] * inv0;
        float v10 = o[nt][2] * inv1, v11 = o[nt][3] * inv1;
        if (mode == 0) {
            *(float2*)(O + (size_t)row0 * DM + col) = make_float2(v00, v01);
            *(float2*)(O + (size_t)row1 * DM + col) = make_float2(v10, v11);
        } else {
            if (mode == 1) {
                float2 a0 = *(float2*)(O + (size_t)row0 * DM + col);
                float2 a1 = *(float2*)(O + (size_t)row1 * DM + col);
                v00 += a0.x; v01 += a0.y; v10 += a1.x; v11 += a1.y;
            }
            *(__half2*)(Oh + (size_t)row0 * DM + col) = __floats2half2_rn(v00, v01);
            *(__half2*)(Oh + (size_t)row1 * DM + col) = __floats2half2_rn(v10, v11);
        }
    }
}

// ---------------- host orchestration ----------------------------------------------
extern "C" void kernel_launch(void* const* d_in, const int* in_sizes, int n_in,
                              void* d_out, int out_size) {
    const float* x     = (const float*)d_in[0];
    const float* ctx   = (const float*)d_in[1];
    const float* qkv_w = (const float*)d_in[2];
    const float* qkv_b = (const float*)d_in[3];
    const float* out_w = (const float*)d_in[4];
    const float* out_b = (const float*)d_in[5];
    const float* w1    = (const float*)d_in[6];
    const float* w3    = (const float*)d_in[7];
    const float* w2    = (const float*)d_in[8];
    const float* n1g   = (const float*)d_in[9];
    const float* n1b   = (const float*)d_in[10];
    const float* n2g   = (const float*)d_in[11];
    const float* n2b   = (const float*)d_in[12];
    float* out = (float*)d_out;

    cudaFuncSetAttribute(mma_gemm_kernel, cudaFuncAttributeMaxDynamicSharedMemorySize, GEMM_SMEM);
    cudaFuncSetAttribute(attn_mma, cudaFuncAttributeMaxDynamicSharedMemorySize, ATTN_SMEM);

    void* p;
    cudaGetSymbolAddress(&p, g_attn);   float* attn   = (float*)p;
    cudaGetSymbolAddress(&p, g_h1);     float* h1     = (float*)p;
    cudaGetSymbolAddress(&p, g_qkv_h);  __half* qkvh  = (__half*)p;
    cudaGetSymbolAddress(&p, g_gateup); __half* gateup = (__half*)p;
    cudaGetSymbolAddress(&p, g_act_h);  __half* ah    = (__half*)p;
    cudaGetSymbolAddress(&p, g_wqkv);   __half* wq  = (__half*)p;
    cudaGetSymbolAddress(&p, g_wout);   __half* wo  = (__half*)p;
    cudaGetSymbolAddress(&p, g_w13);    __half* w13 = (__half*)p;
    cudaGetSymbolAddress(&p, g_w2);     __half* w2p = (__half*)p;
    cudaGetSymbolAddress(&p, g_qx);     __half* qx  = (__half*)p;
    cudaGetSymbolAddress(&p, g_qs);     __half* qs  = (__half*)p;
    cudaGetSymbolAddress(&p, g_kx);     __half* kx  = (__half*)p;
    cudaGetSymbolAddress(&p, g_kc);     __half* kc  = (__half*)p;

    dim3 tb(32, 8);
    // launch order arranged so ncu (-s 5 -c 1) profiles the QKV GEMM (idx 5)
    build_rope_table<<<(MAXPOS * 32 + 255) / 256, 256>>>();                       // 0
    ln_f16_kernel<<<LXX, 256>>>(x,   ah,                    n1g, n1b);            // 1
    ln_f16_kernel<<<LCC, 256>>>(ctx, ah + (size_t)LXX * DM, n1g, n1b);            // 2
    wt_f16_kernel<<<dim3(3 * DM / 32, DM / 32), tb>>>(qkv_w, wq, DM, 3 * DM);     // 3
    wt_f16_kernel<<<dim3(DM / 32, DM / 32),     tb>>>(out_w, wo, DM, DM);         // 4
    mma_gemm_kernel<<<dim3(3 * DM / 128, LTOT / 128), 256, GEMM_SMEM>>>(          // 5 <- ncu
        ah, wq, nullptr, qkvh, qkv_b, nullptr, nullptr, 0, LTOT, 3 * DM, DM);

    // remaining weight preps (needed later)
    wt_f16_kernel<<<dim3(HID / 32, DM / 32),    tb>>>(w1, w13, DM, HID);
    wt_f16_kernel<<<dim3(HID / 32, DM / 32),    tb>>>(w3, w13 + (size_t)HID * DM, DM, HID);
    wt_f16_kernel<<<dim3(DM / 32, HID / 32),    tb>>>(w2, w2p, HID, DM);

    // RoPE: Q (QSCALE) and K (1.0) to contiguous fp16; V stays in qkvh (strided)
    rope_f16_kernel<<<(LXX * 512 + 255) / 256, 256>>>(qkvh, 3 * DM, qx, LXX, POS_X, QSCALE);
    rope_f16_kernel<<<(2048 * 512 + 255) / 256, 256>>>(qkvh + (size_t)(LXX + HWSP) * 3 * DM, 3 * DM, qs, 2048, HWSP, QSCALE);
    rope_f16_kernel<<<(LXX * 512 + 255) / 256, 256>>>(qkvh + DM, 3 * DM, kx, LXX, POS_X, 1.f);
    rope_f16_kernel<<<(LCC * 512 + 255) / 256, 256>>>(qkvh + (size_t)LXX * 3 * DM + DM, 3 * DM, kc, LCC, POS_C, 1.f);

    const __half* vx = qkvh + 2 * DM;
    const __half* vc = qkvh + (size_t)LXX * 3 * DM + 2 * DM;

    // a1 (mode 0: fp32 staging) ; a2 (mode 1: +a1 -> fp16) ; a3 (mode 2: fp16)
    attn_mma<<<dim3(LXX / 64, NH), 128, ATTN_SMEM>>>(qx, kc, vc, 3 * DM,
        attn, nullptr, LCC, 0, 0);
    attn_mma<<<dim3(LXX / 64, NH), 128, ATTN_SMEM>>>(qx, kx, vx, 3 * DM,
        attn, ah, LXX, 1, 1);
    attn_mma<<<dim3(2048 / 64, NH), 128, ATTN_SMEM>>>(qs, kc, vc, 3 * DM,
        nullptr, ah + (size_t)2048 * DM, LCC, 0, 2);

    // out projection + bias + residual -> h1 (fp32)
    mma_gemm_kernel<<<dim3(DM / 128, LOUT / 128), 256, GEMM_SMEM>>>(
        ah, wo, h1, nullptr, out_b, x, ctx, 2048, LOUT, DM, DM);

    // LN2 -> fp16
    ln_f16_kernel<<<LOUT, 256>>>(h1, ah, n2g, n2b);

    // FFN: combined w1|w3 GEMM -> gateup (fp16), fused silu*mul -> fp16, w2 GEMM
    mma_gemm_kernel<<<dim3(2 * HID / 128, LOUT / 128), 256, GEMM_SMEM>>>(
        ah, w13, nullptr, gateup, nullptr, nullptr, nullptr, 0, LOUT, 2 * HID, DM);
    silu_mul_f16_kernel<<<dim3(HID / 256, LOUT), 256>>>(gateup, ah);
    mma_gemm_kernel<<<dim3(DM / 128, LOUT / 128), 256, GEMM_SMEM>>>(
        ah, w2p, out, nullptr, nullptr, h1, h1, LOUT, LOUT, DM, HID);
}

// round 13
// speedup vs baseline: 1.0491x; 1.0491x over previous
#include <cuda_runtime.h>
#include <cuda_fp16.h>
#include <math.h>
#include <stdint.h>

// ---------------- problem constants (from setup_inputs, deterministic) ----------
#define LXX     2048
#define LCC     4096
#define DM      1024
#define NH      16
#define HDIM    64
#define HID     2816
#define LTOT    6144
#define LOUT    4096
#define POS_X   4096
#define POS_C   0
#define HWSP    2048
#define MAXPOS  6144

#define WSCALE     64.0f
#define WSCALE_INV 0.015625f
#define QSCALE     0.125f

// ---------------- scratch (device globals; no runtime allocation) ---------------
__device__ float  g_attn  [LXX * DM];          // a1 fp32 staging
__device__ float  g_h1    [LOUT * DM];
__device__ float  g_cos   [MAXPOS * 32];
__device__ float  g_sin   [MAXPOS * 32];

__device__ __half g_qkv_h [LTOT * 3 * DM];     // QKV projection, fp16
__device__ __half g_gateup[LOUT * 2 * HID];    // FFN1 output, fp16
__device__ __half g_act_h [LOUT * HID];        // A operand of weight GEMMs

// single fp16 weights [N][K], pre-scaled by WSCALE
__device__ __half g_wqkv[3 * DM * DM];
__device__ __half g_wout[DM * DM];
__device__ __half g_w13 [2 * HID * DM];
__device__ __half g_w2  [DM * HID];

// fp16 attention operands (Q pre-scaled by QSCALE)
__device__ __half g_qx[LXX * DM];
__device__ __half g_qs[2048 * DM];
__device__ __half g_kx[LXX * DM];
__device__ __half g_kc[LCC * DM];

// ---------------- helpers (portable: sm_80+ PTX) ----------------------------------
__device__ __forceinline__ uint32_t smem_to_u32(const void* p) {
    uint32_t a;
    asm("{ .reg .u64 t; cvta.to.shared.u64 t, %1; cvt.u32.u64 %0, t; }" : "=r"(a) : "l"(p));
    return a;
}
#define SMEM_SWIZZLE_128B(b) ((b) ^ (((b) >> 3) & 0x70))

__device__ __forceinline__ void cp16(uint32_t s, const void* g) {
    asm volatile("cp.async.cg.shared.global [%0], [%1], 16;" :: "r"(s), "l"(g) : "memory");
}
__device__ __forceinline__ void cp_commit() {
    asm volatile("cp.async.commit_group;" ::: "memory");
}
template<int N> __device__ __forceinline__ void cp_wait() {
    asm volatile("cp.async.wait_group %0;" :: "n"(N) : "memory");
}

__device__ __forceinline__ void ldsm_x4(uint32_t* r, uint32_t addr) {
    asm volatile("ldmatrix.sync.aligned.m8n8.x4.shared.b16 {%0,%1,%2,%3}, [%4];"
        : "=r"(r[0]), "=r"(r[1]), "=r"(r[2]), "=r"(r[3]) : "r"(addr));
}
__device__ __forceinline__ void ldsm_x4_t(uint32_t* r, uint32_t addr) {
    asm volatile("ldmatrix.sync.aligned.m8n8.x4.trans.shared.b16 {%0,%1,%2,%3}, [%4];"
        : "=r"(r[0]), "=r"(r[1]), "=r"(r[2]), "=r"(r[3]) : "r"(addr));
}
__device__ __forceinline__ void mma_f16(float* c, const uint32_t* a, const uint32_t* b) {
    asm volatile("mma.sync.aligned.m16n8k16.row.col.f32.f16.f16.f32 "
        "{%0,%1,%2,%3}, {%4,%5,%6,%7}, {%8,%9}, {%0,%1,%2,%3};"
        : "+f"(c[0]), "+f"(c[1]), "+f"(c[2]), "+f"(c[3])
        : "r"(a[0]), "r"(a[1]), "r"(a[2]), "r"(a[3]), "r"(b[0]), "r"(b[1]));
}

// fast exp on FMA pipe (x <= 0), rel err ~2e-6
__device__ __forceinline__ float fexp(float x) {
    x = fmaxf(x, -87.0f);
    float t = x * 1.4426950408889634f;
    float r = t + 12582912.0f;
    float n = r - 12582912.0f;
    float f = t - n;
    float p = 0.0013298820f;
    p = fmaf(p, f, 0.0096181291f);
    p = fmaf(p, f, 0.0555041087f);
    p = fmaf(p, f, 0.2402265069f);
    p = fmaf(p, f, 0.6931471806f);
    p = fmaf(p, f, 1.0f);
    int ni = (int)n;
    return p * __int_as_float((ni + 127) << 23);
}

// ---------------- rope cos/sin table (fp64 angles) -------------------------------
__global__ void build_rope_table() {
    int idx = blockIdx.x * blockDim.x + threadIdx.x;
    if (idx >= MAXPOS * 32) return;
    int pos = idx >> 5, j = idx & 31;
    double inv = pow(10000.0, -((double)(2 * j)) / 64.0);
    double ang = (double)pos * inv;
    g_cos[idx] = (float)cos(ang);
    g_sin[idx] = (float)sin(ang);
}

// ---------------- LayerNorm fused with fp16 output ---------------------------------
__global__ void ln_f16_kernel(const float* __restrict__ in,
                              __half* __restrict__ out,
                              const float* __restrict__ gam,
                              const float* __restrict__ bet) {
    __shared__ float sh[32];
    __shared__ float s_mean, s_rstd;
    int row = blockIdx.x, t = threadIdx.x;
    const float* x = in + (size_t)row * DM;
    float v[4];
    float s = 0.f;
#pragma unroll
    for (int i = 0; i < 4; i++) { v[i] = x[t + 256 * i]; s += v[i]; }
#pragma unroll
    for (int o = 16; o; o >>= 1) s += __shfl_xor_sync(0xffffffffu, s, o);
    if ((t & 31) == 0) sh[t >> 5] = s;
    __syncthreads();
    if (t < 32) {
        float z = (t < 8) ? sh[t] : 0.f;
#pragma unroll
        for (int o = 4; o; o >>= 1) z += __shfl_xor_sync(0xffffffffu, z, o);
        if (t == 0) s_mean = z * (1.f / 1024.f);
    }
    __syncthreads();
    float mean = s_mean;
    float q = 0.f;
#pragma unroll
    for (int i = 0; i < 4; i++) { float d = v[i] - mean; q += d * d; }
#pragma unroll
    for (int o = 16; o; o >>= 1) q += __shfl_xor_sync(0xffffffffu, q, o);
    if ((t & 31) == 0) sh[t >> 5] = q;
    __syncthreads();
    if (t < 32) {
        float z = (t < 8) ? sh[t] : 0.f;
#pragma unroll
        for (int o = 4; o; o >>= 1) z += __shfl_xor_sync(0xffffffffu, z, o);
        if (t == 0) s_rstd = rsqrtf(z * (1.f / 1024.f) + 1e-5f);
    }
    __syncthreads();
    float rstd = s_rstd;
#pragma unroll
    for (int i = 0; i < 4; i++) {
        int c = t + 256 * i;
        float r = (v[i] - mean) * rstd * gam[c] + bet[c];
        out[(size_t)row * DM + c] = __float2half(r);
    }
}

// ---------------- RoPE: fp16 strided in -> fp16 contiguous out ---------------------
__global__ void rope_f16_kernel(const __half* __restrict__ src, int lds,
                                __half* __restrict__ out,
                                int L, int pos0, float scale) {
    int idx = blockIdx.x * blockDim.x + threadIdx.x;
    if (idx >= L * 512) return;
    int j = idx & 31, h = (idx >> 5) & 15, l = idx >> 9;
    int pos = pos0 + l;
    float c = g_cos[pos * 32 + j], s = g_sin[pos * 32 + j];
    const __half* p = src + (size_t)l * lds + h * HDIM;
    float t1 = __half2float(p[j]), t2 = __half2float(p[j + 32]);
    size_t o = (size_t)l * DM + h * HDIM;
    out[o + j]      = __float2half((t1 * c - t2 * s) * scale);
    out[o + j + 32] = __float2half((t2 * c + t1 * s) * scale);
}

// ---------------- weight transpose + single fp16 (pre-scaled by WSCALE) ------------
__global__ void wt_f16_kernel(const float* __restrict__ w,
                              __half* __restrict__ o, int K, int N) {
    __shared__ float t[32][33];
    int n0 = blockIdx.x * 32, k0 = blockIdx.y * 32;
    int tx = threadIdx.x, ty = threadIdx.y;
#pragma unroll
    for (int i = 0; i < 32; i += 8)
        t[ty + i][tx] = w[(size_t)(k0 + ty + i) * N + n0 + tx];
    __syncthreads();
#pragma unroll
    for (int i = 0; i < 32; i += 8) {
        int n = n0 + ty + i, k = k0 + tx;
        o[(size_t)n * K + k] = __float2half(t[tx][ty + i] * WSCALE);
    }
}

// ---------------- silu(g)*u (fp16 in) fused with fp16 output ------------------------
__global__ void silu_mul_f16_kernel(const __half* __restrict__ gu,
                                    __half* __restrict__ out) {
    int col = blockIdx.x * 256 + threadIdx.x;     // < HID (11 blocks x 256 = 2816)
    int row = blockIdx.y;
    float g = __half2float(gu[(size_t)row * (2 * HID) + col]);
    float u = __half2float(gu[(size_t)row * (2 * HID) + HID + col]);
    float r = (g / (1.f + __expf(-g))) * u;
    out[(size_t)row * HID + col] = __float2half(r);
}

// ---------------- fp16 single-pass GEMM, cp.async 2-stage pipeline ------------------
// C = (1/WSCALE) * A[M][K] * B[N][K]^T (+bias). Out fp32 (+residual) or fp16 (Ch).
static const int GEMM_SMEM = 2 * 2 * 16384;   // 65536

__global__ void __launch_bounds__(256, 2)
mma_gemm_kernel(const __half* __restrict__ A, const __half* __restrict__ B,
                float* __restrict__ C, __half* __restrict__ Ch,
                const float* __restrict__ bias,
                const float* __restrict__ res0, const float* __restrict__ res1, int split,
                int M, int N, int K) {
    extern __shared__ char smem[];
    uint32_t sbase = smem_to_u32(smem);

    int tid = threadIdx.x;
    int wid = tid >> 5, lane = tid & 31;
    int wr = wid >> 2, wc = wid & 3;
    int m0 = blockIdx.y * 128, n0 = blockIdx.x * 128;

    int lr  = lane & 7;
    int lq  = lane >> 3;
    int qlo = lq & 1, qhi = lq >> 1;

    uint32_t aoff[4];
#pragma unroll
    for (int mt = 0; mt < 4; mt++) {
        int row = wr * 64 + mt * 16 + qlo * 8 + lr;
        aoff[mt] = (uint32_t)(row * 128) + (uint32_t)((qhi * 16) ^ ((row & 7) * 16));
    }
    uint32_t boff[2];
#pragma unroll
    for (int np = 0; np < 2; np++) {
        int row = wc * 32 + np * 16 + qhi * 8 + lr;
        boff[np] = (uint32_t)(row * 128) + (uint32_t)((qlo * 16) ^ ((row & 7) * 16));
    }

    auto issue = [&](int st, int kc0) {
        uint32_t base = sbase + (uint32_t)st * 32768;
#pragma unroll
        for (int it = 0; it < 4; it++) {
            int idx = tid + it * 256;
            int r = idx >> 3, q = idx & 7;
            uint32_t so = SMEM_SWIZZLE_128B((uint32_t)(r * 128 + q * 16));
            cp16(base + so,         A + (size_t)(m0 + r) * K + kc0 + q * 8);
            cp16(base + 16384 + so, B + (size_t)(n0 + r) * K + kc0 + q * 8);
        }
        cp_commit();
    };

    float acc[4][4][4] = {};
    int nchunks = K >> 6;

    issue(0, 0);
    for (int kc = 0; kc < nchunks; kc++) {
        int st = kc & 1;
        if (kc + 1 < nchunks) { issue(st ^ 1, (kc + 1) << 6); cp_wait<1>(); }
        else                  { cp_wait<0>(); }
        __syncthreads();

        uint32_t sA = sbase + (uint32_t)st * 32768;
        uint32_t sB = sA + 16384;

#pragma unroll
        for (int ks = 0; ks < 4; ks++) {
            uint32_t kx = (uint32_t)(ks << 5);
            uint32_t bh[2][4];
#pragma unroll
            for (int np = 0; np < 2; np++)
                ldsm_x4(bh[np], sB + (boff[np] ^ kx));
#pragma unroll
            for (int mt = 0; mt < 4; mt++) {
                uint32_t ah[4];
                ldsm_x4(ah, sA + (aoff[mt] ^ kx));
#pragma unroll
                for (int nt = 0; nt < 4; nt++)
                    mma_f16(acc[mt][nt], ah, &bh[nt >> 1][(nt & 1) * 2]);
            }
        }
        __syncthreads();
    }

    int g = lane >> 2, tg = lane & 3;
#pragma unroll
    for (int mt = 0; mt < 4; mt++) {
#pragma unroll
        for (int half = 0; half < 2; half++) {
            int row = m0 + wr * 64 + mt * 16 + g + half * 8;
            const float* rp = nullptr;
            if (res0) rp = ((row < split) ? res0 : res1) + (size_t)row * N;
#pragma unroll
            for (int nt = 0; nt < 4; nt++) {
                int col = n0 + wc * 32 + nt * 8 + tg * 2;
                float vx = acc[mt][nt][half * 2 + 0] * WSCALE_INV;
                float vy = acc[mt][nt][half * 2 + 1] * WSCALE_INV;
                if (bias) { vx += bias[col]; vy += bias[col + 1]; }
                if (Ch) {
                    *(__half2*)(Ch + (size_t)row * N + col) = __floats2half2_rn(vx, vy);
                } else {
                    if (rp) { vx += rp[col]; vy += rp[col + 1]; }
                    *(float2*)(C + (size_t)row * N + col) = make_float2(vx, vy);
                }
            }
        }
    }
}

// ---------------- fp16 single-pass flash attention, cp.async 2-stage ----------------
// Q single fp16 (pre-scaled QSCALE), K single fp16, V single fp16 (strided ldv).
// mode 0: write fp32 O; 1: read fp32 O, add, write fp16; 2: write fp16.
static const int ATTN_SMEM = 2 * 2 * 8192;    // 32768

__global__ void __launch_bounds__(128)
attn_mma(const __half* __restrict__ Q, const __half* __restrict__ K,
         const __half* __restrict__ V, int ldv,
         float* __restrict__ O, __half* __restrict__ Oh,
         int LK, int causal, int mode) {
    extern __shared__ char smema[];
    uint32_t sb = smem_to_u32(smema);

    int tid = threadIdx.x;
    int wid = tid >> 5, lane = tid & 31;
    int g = lane >> 2, tg = lane & 3;
    int lr = lane & 7, qlo = (lane >> 3) & 1, qhi = lane >> 4;
    int q0 = blockIdx.x * 64;
    int h  = blockIdx.y;

    // ---- stage Q, extract fragments ----
#pragma unroll
    for (int it = 0; it < 4; it++) {
        int e = tid + it * 128;           // 0..511
        int row = e >> 3, q = e & 7;
        uint32_t off = (uint32_t)(row * 128) + (uint32_t)((q * 16) ^ ((row & 7) * 16));
        *(uint4*)(smema + off) = *(const uint4*)(Q + (size_t)(q0 + row) * DM + h * HDIM + q * 8);
    }
    __syncthreads();
    uint32_t qf[4][4];
    {
        int arow = wid * 16 + qlo * 8 + lr;
        uint32_t abase = (uint32_t)(arow * 128) + (uint32_t)((qhi * 16) ^ ((arow & 7) * 16));
#pragma unroll
        for (int ks = 0; ks < 4; ks++)
            ldsm_x4(qf[ks], sb + (abase ^ (uint32_t)(ks << 5)));
    }
    __syncthreads();

    auto issue = [&](int st, int k0) {
        uint32_t base = sb + (uint32_t)st * 16384;
#pragma unroll
        for (int it = 0; it < 4; it++) {
            int e = tid + it * 128;
            int row = e >> 3, q = e & 7;
            uint32_t off = (uint32_t)(row * 128) + (uint32_t)((q * 16) ^ ((row & 7) * 16));
            cp16(base + off,        K + (size_t)(k0 + row) * DM + h * HDIM + q * 8);
            cp16(base + 8192 + off, V + (size_t)(k0 + row) * ldv + h * HDIM + q * 8);
        }
        cp_commit();
    };

    float o[8][4] = {};
    float m0r = -1e30f, m1r = -1e30f, l0r = 0.f, l1r = 0.f;

    int ntiles = causal ? ((int)blockIdx.x + 1) : (LK >> 6);
    issue(0, 0);
    for (int kt = 0; kt < ntiles; kt++) {
        int k0 = kt << 6;
        int st = kt & 1;
        if (kt + 1 < ntiles) { issue(st ^ 1, (kt + 1) << 6); cp_wait<1>(); }
        else                 { cp_wait<0>(); }
        __syncthreads();

        uint32_t sK = sb + (uint32_t)st * 16384;
        uint32_t sV = sK + 8192;

        // ---- S = Q K^T (single pass) ----
        float s[8][4] = {};
#pragma unroll
        for (int ks = 0; ks < 4; ks++) {
            uint32_t kx = (uint32_t)(ks << 5);
            uint32_t bf[4][4];
#pragma unroll
            for (int np = 0; np < 4; np++) {
                int br = np * 16 + qhi * 8 + lr;
                uint32_t boff = (uint32_t)(br * 128) +
                                (uint32_t)(((qlo * 16) ^ (int)kx) ^ ((br & 7) * 16));
                ldsm_x4(bf[np], sK + boff);
            }
#pragma unroll
            for (int nt = 0; nt < 8; nt++)
                mma_f16(s[nt], qf[ks], &bf[nt >> 1][(nt & 1) * 2]);
        }

        // ---- causal mask (diagonal tile only) ----
        if (causal && kt == (int)blockIdx.x) {
            int r0 = q0 + wid * 16 + g, r1 = r0 + 8;
#pragma unroll
            for (int nt = 0; nt < 8; nt++) {
                int kbase = k0 + nt * 8 + tg * 2;
                if (kbase > r0)     s[nt][0] = -1e30f;
                if (kbase + 1 > r0) s[nt][1] = -1e30f;
                if (kbase > r1)     s[nt][2] = -1e30f;
                if (kbase + 1 > r1) s[nt][3] = -1e30f;
            }
        }

        // ---- online softmax ----
        float mx0 = -1e30f, mx1 = -1e30f;
#pragma unroll
        for (int nt = 0; nt < 8; nt++) {
            mx0 = fmaxf(mx0, fmaxf(s[nt][0], s[nt][1]));
            mx1 = fmaxf(mx1, fmaxf(s[nt][2], s[nt][3]));
        }
        mx0 = fmaxf(mx0, __shfl_xor_sync(0xffffffffu, mx0, 1));
        mx0 = fmaxf(mx0, __shfl_xor_sync(0xffffffffu, mx0, 2));
        mx1 = fmaxf(mx1, __shfl_xor_sync(0xffffffffu, mx1, 1));
        mx1 = fmaxf(mx1, __shfl_xor_sync(0xffffffffu, mx1, 2));
        float mn0 = fmaxf(m0r, mx0), mn1 = fmaxf(m1r, mx1);
        float al0 = fexp(m0r - mn0), al1 = fexp(m1r - mn1);
        float sum0 = 0.f, sum1 = 0.f;
#pragma unroll
        for (int nt = 0; nt < 8; nt++) {
            s[nt][0] = fexp(s[nt][0] - mn0);
            s[nt][1] = fexp(s[nt][1] - mn0);
            s[nt][2] = fexp(s[nt][2] - mn1);
            s[nt][3] = fexp(s[nt][3] - mn1);
            sum0 += s[nt][0] + s[nt][1];
            sum1 += s[nt][2] + s[nt][3];
        }
        sum0 += __shfl_xor_sync(0xffffffffu, sum0, 1);
        sum0 += __shfl_xor_sync(0xffffffffu, sum0, 2);
        sum1 += __shfl_xor_sync(0xffffffffu, sum1, 1);
        sum1 += __shfl_xor_sync(0xffffffffu, sum1, 2);
        l0r = l0r * al0 + sum0; m0r = mn0;
        l1r = l1r * al1 + sum1; m1r = mn1;
#pragma unroll
        for (int nt = 0; nt < 8; nt++) {
            o[nt][0] *= al0; o[nt][1] *= al0;
            o[nt][2] *= al1; o[nt][3] *= al1;
        }

        // ---- O += P V (single pass), V via ldmatrix.trans ----
#pragma unroll
        for (int kb = 0; kb < 4; kb++) {
            uint32_t ph[4];
            {
                __half2 p0 = __floats2half2_rn(s[2 * kb][0],     s[2 * kb][1]);
                __half2 p1 = __floats2half2_rn(s[2 * kb][2],     s[2 * kb][3]);
                __half2 p2 = __floats2half2_rn(s[2 * kb + 1][0], s[2 * kb + 1][1]);
                __half2 p3 = __floats2half2_rn(s[2 * kb + 1][2], s[2 * kb + 1][3]);
                ph[0] = *(uint32_t*)&p0; ph[1] = *(uint32_t*)&p1;
                ph[2] = *(uint32_t*)&p2; ph[3] = *(uint32_t*)&p3;
            }
            uint32_t vf[4][4];
            int vr = kb * 16 + qlo * 8 + lr;
            uint32_t vrow = (uint32_t)(vr * 128);
            uint32_t vsw  = (uint32_t)((vr & 7) * 16);
#pragma unroll
            for (int np = 0; np < 4; np++)
                ldsm_x4_t(vf[np], sV + vrow + (((uint32_t)(np * 32 + qhi * 16)) ^ vsw));
#pragma unroll
            for (int nt = 0; nt < 8; nt++)
                mma_f16(o[nt], ph, &vf[nt >> 1][(nt & 1) * 2]);
        }
        __syncthreads();
    }

    // ---- epilogue ----
    float inv0 = 1.f / l0r, inv1 = 1.f / l1r;
    int row0 = q0 + wid * 16 + g;
    int row1 = row0 + 8;
#pragma unroll
    for (int nt = 0; nt < 8; nt++) {
        int col = h * HDIM + nt * 8 + tg * 2;
        float v00 = o[nt][0] * inv0, v01 = o[nt][1] * inv0;
        float v10 = o[nt][2] * inv1, v11 = o[nt][3] * inv1;
        if (mode == 0) {
            *(float2*)(O + (size_t)row0 * DM + col) = make_float2(v00, v01);
            *(float2*)(O + (size_t)row1 * DM + col) = make_float2(v10, v11);
        } else {
            if (mode == 1) {
                float2 a0 = *(float2*)(O + (size_t)row0 * DM + col);
                float2 a1 = *(float2*)(O + (size_t)row1 * DM + col);
                v00 += a0.x; v01 += a0.y; v10 += a1.x; v11 += a1.y;
            }
            *(__half2*)(Oh + (size_t)row0 * DM + col) = __floats2half2_rn(v00, v01);
            *(__half2*)(Oh + (size_t)row1 * DM + col) = __floats2half2_rn(v10, v11);
        }
    }
}

// ---------------- host orchestration ----------------------------------------------
extern "C" void kernel_launch(void* const* d_in, const int* in_sizes, int n_in,
                              void* d_out, int out_size) {
    const float* x     = (const float*)d_in[0];
    const float* ctx   = (const float*)d_in[1];
    const float* qkv_w = (const float*)d_in[2];
    const float* qkv_b = (const float*)d_in[3];
    const float* out_w = (const float*)d_in[4];
    const float* out_b = (const float*)d_in[5];
    const float* w1    = (const float*)d_in[6];
    const float* w3    = (const float*)d_in[7];
    const float* w2    = (const float*)d_in[8];
    const float* n1g   = (const float*)d_in[9];
    const float* n1b   = (const float*)d_in[10];
    const float* n2g   = (const float*)d_in[11];
    const float* n2b   = (const float*)d_in[12];
    float* out = (float*)d_out;

    cudaFuncSetAttribute(mma_gemm_kernel, cudaFuncAttributeMaxDynamicSharedMemorySize, GEMM_SMEM);
    cudaFuncSetAttribute(attn_mma, cudaFuncAttributeMaxDynamicSharedMemorySize, ATTN_SMEM);

    void* p;
    cudaGetSymbolAddress(&p, g_attn);   float* attn   = (float*)p;
    cudaGetSymbolAddress(&p, g_h1);     float* h1     = (float*)p;
    cudaGetSymbolAddress(&p, g_qkv_h);  __half* qkvh  = (__half*)p;
    cudaGetSymbolAddress(&p, g_gateup); __half* gateup = (__half*)p;
    cudaGetSymbolAddress(&p, g_act_h);  __half* ah    = (__half*)p;
    cudaGetSymbolAddress(&p, g_wqkv);   __half* wq  = (__half*)p;
    cudaGetSymbolAddress(&p, g_wout);   __half* wo  = (__half*)p;
    cudaGetSymbolAddress(&p, g_w13);    __half* w13 = (__half*)p;
    cudaGetSymbolAddress(&p, g_w2);     __half* w2p = (__half*)p;
    cudaGetSymbolAddress(&p, g_qx);     __half* qx  = (__half*)p;
    cudaGetSymbolAddress(&p, g_qs);     __half* qs  = (__half*)p;
    cudaGetSymbolAddress(&p, g_kx);     __half* kx  = (__half*)p;
    cudaGetSymbolAddress(&p, g_kc);     __half* kc  = (__half*)p;

    dim3 tb(32, 8);
    build_rope_table<<<(MAXPOS * 32 + 255) / 256, 256>>>();

    // weight transpose + single fp16 (pre-scaled); w1,w3 packed [5632][1024]
    wt_f16_kernel<<<dim3(3 * DM / 32, DM / 32), tb>>>(qkv_w, wq, DM, 3 * DM);
    wt_f16_kernel<<<dim3(DM / 32, DM / 32),     tb>>>(out_w, wo, DM, DM);
    wt_f16_kernel<<<dim3(HID / 32, DM / 32),    tb>>>(w1, w13, DM, HID);
    wt_f16_kernel<<<dim3(HID / 32, DM / 32),    tb>>>(w3, w13 + (size_t)HID * DM, DM, HID);
    wt_f16_kernel<<<dim3(DM / 32, HID / 32),    tb>>>(w2, w2p, HID, DM);

    // LN1 -> fp16 A buffer [LTOT][DM]
    ln_f16_kernel<<<LXX, 256>>>(x,   ah,                    n1g, n1b);
    ln_f16_kernel<<<LCC, 256>>>(ctx, ah + (size_t)LXX * DM, n1g, n1b);

    // QKV projection (fp16 out, bias)
    mma_gemm_kernel<<<dim3(3 * DM / 128, LTOT / 128), 256, GEMM_SMEM>>>(
        ah, wq, nullptr, qkvh, qkv_b, nullptr, nullptr, 0, LTOT, 3 * DM, DM);

    // RoPE: Q (QSCALE) and K (1.0) to contiguous fp16; V stays in qkvh (strided)
    rope_f16_kernel<<<(LXX * 512 + 255) / 256, 256>>>(qkvh, 3 * DM, qx, LXX, POS_X, QSCALE);
    rope_f16_kernel<<<(2048 * 512 + 255) / 256, 256>>>(qkvh + (size_t)(LXX + HWSP) * 3 * DM, 3 * DM, qs, 2048, HWSP, QSCALE);
    rope_f16_kernel<<<(LXX * 512 + 255) / 256, 256>>>(qkvh + DM, 3 * DM, kx, LXX, POS_X, 1.f);
    rope_f16_kernel<<<(LCC * 512 + 255) / 256, 256>>>(qkvh + (size_t)LXX * 3 * DM + DM, 3 * DM, kc, LCC, POS_C, 1.f);

    const __half* vx = qkvh + 2 * DM;                          // rows 0..2047 (strided)
    const __half* vc = qkvh + (size_t)LXX * 3 * DM + 2 * DM;   // rows 2048..6143 (strided)

    // a1 (mode 0: fp32 staging) ; a2 (mode 1: +a1 -> fp16) ; a3 (mode 2: fp16)
    attn_mma<<<dim3(LXX / 64, NH), 128, ATTN_SMEM>>>(qx, kc, vc, 3 * DM,
        attn, nullptr, LCC, 0, 0);
    attn_mma<<<dim3(LXX / 64, NH), 128, ATTN_SMEM>>>(qx, kx, vx, 3 * DM,
        attn, ah, LXX, 1, 1);
    attn_mma<<<dim3(2048 / 64, NH), 128, ATTN_SMEM>>>(qs, kc, vc, 3 * DM,
        nullptr, ah + (size_t)2048 * DM, LCC, 0, 2);

    // out projection + bias + residual -> h1 (fp32)
    mma_gemm_kernel<<<dim3(DM / 128, LOUT / 128), 256, GEMM_SMEM>>>(
        ah, wo, h1, nullptr, out_b, x, ctx, 2048, LOUT, DM, DM);

    // LN2 -> fp16
    ln_f16_kernel<<<LOUT, 256>>>(h1, ah, n2g, n2b);

    // FFN: combined w1|w3 GEMM -> gateup (fp16), fused silu*mul -> fp16, w2 GEMM
    mma_gemm_kernel<<<dim3(2 * HID / 128, LOUT / 128), 256, GEMM_SMEM>>>(
        ah, w13, nullptr, gateup, nullptr, nullptr, nullptr, 0, LOUT, 2 * HID, DM);
    silu_mul_f16_kernel<<<dim3(HID / 256, LOUT), 256>>>(gateup, ah);
    mma_gemm_kernel<<<dim3(DM / 128, LOUT / 128), 256, GEMM_SMEM>>>(
        ah, w2p, out, nullptr, nullptr, h1, h1, LOUT, LOUT, DM, HID);
}

// round 14
// speedup vs baseline: 1.0778x; 1.0274x over previous
#include <cuda_runtime.h>
#include <cuda_fp16.h>
#include <math.h>
#include <stdint.h>

// ---------------- problem constants (from setup_inputs, deterministic) ----------
#define LXX     2048
#define LCC     4096
#define DM      1024
#define NH      16
#define HDIM    64
#define HID     2816
#define LTOT    6144
#define LOUT    4096
#define POS_X   4096
#define POS_C   0
#define HWSP    2048
#define MAXPOS  6144

#define WSCALE     64.0f
#define WSCALE_INV 0.015625f
#define QSCALE     0.125f

// ---------------- scratch (device globals; no runtime allocation) ---------------
__device__ float  g_attn  [LXX * DM];          // a1 fp32 staging
__device__ float  g_h1    [LOUT * DM];
__device__ float  g_cos   [MAXPOS * 32];
__device__ float  g_sin   [MAXPOS * 32];

__device__ __half g_qkv_h [LTOT * 3 * DM];     // QKV projection, fp16
__device__ __half g_gateup[LOUT * 2 * HID];    // FFN1 output, fp16
__device__ __half g_act_h [LOUT * HID];        // A operand of weight GEMMs

// single fp16 weights [N][K], pre-scaled by WSCALE
__device__ __half g_wqkv[3 * DM * DM];
__device__ __half g_wout[DM * DM];
__device__ __half g_w13 [2 * HID * DM];
__device__ __half g_w2  [DM * HID];

// fp16 attention operands (Q pre-scaled by QSCALE)
__device__ __half g_qx[LXX * DM];
__device__ __half g_qs[2048 * DM];
__device__ __half g_kx[LXX * DM];
__device__ __half g_kc[LCC * DM];

// ---------------- helpers (portable: sm_80+ PTX) ----------------------------------
__device__ __forceinline__ uint32_t smem_to_u32(const void* p) {
    uint32_t a;
    asm("{ .reg .u64 t; cvta.to.shared.u64 t, %1; cvt.u32.u64 %0, t; }" : "=r"(a) : "l"(p));
    return a;
}
#define SMEM_SWIZZLE_128B(b) ((b) ^ (((b) >> 3) & 0x70))

__device__ __forceinline__ void cp16(uint32_t s, const void* g) {
    asm volatile("cp.async.cg.shared.global [%0], [%1], 16;" :: "r"(s), "l"(g) : "memory");
}
__device__ __forceinline__ void cp_commit() {
    asm volatile("cp.async.commit_group;" ::: "memory");
}
template<int N> __device__ __forceinline__ void cp_wait() {
    asm volatile("cp.async.wait_group %0;" :: "n"(N) : "memory");
}

__device__ __forceinline__ void ldsm_x4(uint32_t* r, uint32_t addr) {
    asm volatile("ldmatrix.sync.aligned.m8n8.x4.shared.b16 {%0,%1,%2,%3}, [%4];"
        : "=r"(r[0]), "=r"(r[1]), "=r"(r[2]), "=r"(r[3]) : "r"(addr));
}
__device__ __forceinline__ void ldsm_x4_t(uint32_t* r, uint32_t addr) {
    asm volatile("ldmatrix.sync.aligned.m8n8.x4.trans.shared.b16 {%0,%1,%2,%3}, [%4];"
        : "=r"(r[0]), "=r"(r[1]), "=r"(r[2]), "=r"(r[3]) : "r"(addr));
}
__device__ __forceinline__ void mma_f16(float* c, const uint32_t* a, const uint32_t* b) {
    asm volatile("mma.sync.aligned.m16n8k16.row.col.f32.f16.f16.f32 "
        "{%0,%1,%2,%3}, {%4,%5,%6,%7}, {%8,%9}, {%0,%1,%2,%3};"
        : "+f"(c[0]), "+f"(c[1]), "+f"(c[2]), "+f"(c[3])
        : "r"(a[0]), "r"(a[1]), "r"(a[2]), "r"(a[3]), "r"(b[0]), "r"(b[1]));
}

// fast exp on FMA pipe (x <= 0), rel err ~2e-6
__device__ __forceinline__ float fexp(float x) {
    x = fmaxf(x, -87.0f);
    float t = x * 1.4426950408889634f;
    float r = t + 12582912.0f;
    float n = r - 12582912.0f;
    float f = t - n;
    float p = 0.0013298820f;
    p = fmaf(p, f, 0.0096181291f);
    p = fmaf(p, f, 0.0555041087f);
    p = fmaf(p, f, 0.2402265069f);
    p = fmaf(p, f, 0.6931471806f);
    p = fmaf(p, f, 1.0f);
    int ni = (int)n;
    return p * __int_as_float((ni + 127) << 23);
}

// ---------------- rope cos/sin table (fp64 angles) -------------------------------
__global__ void build_rope_table() {
    int idx = blockIdx.x * blockDim.x + threadIdx.x;
    if (idx >= MAXPOS * 32) return;
    int pos = idx >> 5, j = idx & 31;
    double inv = pow(10000.0, -((double)(2 * j)) / 64.0);
    double ang = (double)pos * inv;
    g_cos[idx] = (float)cos(ang);
    g_sin[idx] = (float)sin(ang);
}

// ---------------- LayerNorm fused with fp16 output ---------------------------------
__global__ void ln_f16_kernel(const float* __restrict__ in,
                              __half* __restrict__ out,
                              const float* __restrict__ gam,
                              const float* __restrict__ bet) {
    __shared__ float sh[32];
    __shared__ float s_mean, s_rstd;
    int row = blockIdx.x, t = threadIdx.x;
    const float* x = in + (size_t)row * DM;
    float v[4];
    float s = 0.f;
#pragma unroll
    for (int i = 0; i < 4; i++) { v[i] = x[t + 256 * i]; s += v[i]; }
#pragma unroll
    for (int o = 16; o; o >>= 1) s += __shfl_xor_sync(0xffffffffu, s, o);
    if ((t & 31) == 0) sh[t >> 5] = s;
    __syncthreads();
    if (t < 32) {
        float z = (t < 8) ? sh[t] : 0.f;
#pragma unroll
        for (int o = 4; o; o >>= 1) z += __shfl_xor_sync(0xffffffffu, z, o);
        if (t == 0) s_mean = z * (1.f / 1024.f);
    }
    __syncthreads();
    float mean = s_mean;
    float q = 0.f;
#pragma unroll
    for (int i = 0; i < 4; i++) { float d = v[i] - mean; q += d * d; }
#pragma unroll
    for (int o = 16; o; o >>= 1) q += __shfl_xor_sync(0xffffffffu, q, o);
    if ((t & 31) == 0) sh[t >> 5] = q;
    __syncthreads();
    if (t < 32) {
        float z = (t < 8) ? sh[t] : 0.f;
#pragma unroll
        for (int o = 4; o; o >>= 1) z += __shfl_xor_sync(0xffffffffu, z, o);
        if (t == 0) s_rstd = rsqrtf(z * (1.f / 1024.f) + 1e-5f);
    }
    __syncthreads();
    float rstd = s_rstd;
#pragma unroll
    for (int i = 0; i < 4; i++) {
        int c = t + 256 * i;
        float r = (v[i] - mean) * rstd * gam[c] + bet[c];
        out[(size_t)row * DM + c] = __float2half(r);
    }
}

// ---------------- RoPE: fp16 strided in -> fp16 contiguous out ---------------------
__global__ void rope_f16_kernel(const __half* __restrict__ src, int lds,
                                __half* __restrict__ out,
                                int L, int pos0, float scale) {
    int idx = blockIdx.x * blockDim.x + threadIdx.x;
    if (idx >= L * 512) return;
    int j = idx & 31, h = (idx >> 5) & 15, l = idx >> 9;
    int pos = pos0 + l;
    float c = g_cos[pos * 32 + j], s = g_sin[pos * 32 + j];
    const __half* p = src + (size_t)l * lds + h * HDIM;
    float t1 = __half2float(p[j]), t2 = __half2float(p[j + 32]);
    size_t o = (size_t)l * DM + h * HDIM;
    out[o + j]      = __float2half((t1 * c - t2 * s) * scale);
    out[o + j + 32] = __float2half((t2 * c + t1 * s) * scale);
}

// ---------------- weight transpose + single fp16 (pre-scaled by WSCALE) ------------
__global__ void wt_f16_kernel(const float* __restrict__ w,
                              __half* __restrict__ o, int K, int N) {
    __shared__ float t[32][33];
    int n0 = blockIdx.x * 32, k0 = blockIdx.y * 32;
    int tx = threadIdx.x, ty = threadIdx.y;
#pragma unroll
    for (int i = 0; i < 32; i += 8)
        t[ty + i][tx] = w[(size_t)(k0 + ty + i) * N + n0 + tx];
    __syncthreads();
#pragma unroll
    for (int i = 0; i < 32; i += 8) {
        int n = n0 + ty + i, k = k0 + tx;
        o[(size_t)n * K + k] = __float2half(t[tx][ty + i] * WSCALE);
    }
}

// ---------------- silu(g)*u (fp16 in) fused with fp16 output ------------------------
__global__ void silu_mul_f16_kernel(const __half* __restrict__ gu,
                                    __half* __restrict__ out) {
    int col = blockIdx.x * 256 + threadIdx.x;     // < HID (11 blocks x 256 = 2816)
    int row = blockIdx.y;
    float g = __half2float(gu[(size_t)row * (2 * HID) + col]);
    float u = __half2float(gu[(size_t)row * (2 * HID) + HID + col]);
    float r = (g / (1.f + __expf(-g))) * u;
    out[(size_t)row * HID + col] = __float2half(r);
}

// ---------------- fp16 single-pass GEMM, cp.async 2-stage pipeline ------------------
// C = (1/WSCALE) * A[M][K] * B[N][K]^T (+bias). Out fp32 (+residual) or fp16 (Ch).
static const int GEMM_SMEM = 2 * 2 * 16384;   // 65536

__global__ void __launch_bounds__(256, 2)
mma_gemm_kernel(const __half* __restrict__ A, const __half* __restrict__ B,
                float* __restrict__ C, __half* __restrict__ Ch,
                const float* __restrict__ bias,
                const float* __restrict__ res0, const float* __restrict__ res1, int split,
                int M, int N, int K) {
    extern __shared__ char smem[];
    uint32_t sbase = smem_to_u32(smem);

    int tid = threadIdx.x;
    int wid = tid >> 5, lane = tid & 31;
    int wr = wid >> 2, wc = wid & 3;
    int m0 = blockIdx.y * 128, n0 = blockIdx.x * 128;

    int lr  = lane & 7;
    int lq  = lane >> 3;
    int qlo = lq & 1, qhi = lq >> 1;

    uint32_t aoff[4];
#pragma unroll
    for (int mt = 0; mt < 4; mt++) {
        int row = wr * 64 + mt * 16 + qlo * 8 + lr;
        aoff[mt] = (uint32_t)(row * 128) + (uint32_t)((qhi * 16) ^ ((row & 7) * 16));
    }
    uint32_t boff[2];
#pragma unroll
    for (int np = 0; np < 2; np++) {
        int row = wc * 32 + np * 16 + qhi * 8 + lr;
        boff[np] = (uint32_t)(row * 128) + (uint32_t)((qlo * 16) ^ ((row & 7) * 16));
    }

    auto issue = [&](int st, int kc0) {
        uint32_t base = sbase + (uint32_t)st * 32768;
#pragma unroll
        for (int it = 0; it < 4; it++) {
            int idx = tid + it * 256;
            int r = idx >> 3, q = idx & 7;
            uint32_t so = SMEM_SWIZZLE_128B((uint32_t)(r * 128 + q * 16));
            cp16(base + so,         A + (size_t)(m0 + r) * K + kc0 + q * 8);
            cp16(base + 16384 + so, B + (size_t)(n0 + r) * K + kc0 + q * 8);
        }
        cp_commit();
    };

    float acc[4][4][4] = {};
    int nchunks = K >> 6;

    issue(0, 0);
    for (int kc = 0; kc < nchunks; kc++) {
        int st = kc & 1;
        if (kc + 1 < nchunks) { issue(st ^ 1, (kc + 1) << 6); cp_wait<1>(); }
        else                  { cp_wait<0>(); }
        __syncthreads();

        uint32_t sA = sbase + (uint32_t)st * 32768;
        uint32_t sB = sA + 16384;

#pragma unroll
        for (int ks = 0; ks < 4; ks++) {
            uint32_t kx = (uint32_t)(ks << 5);
            uint32_t bh[2][4];
#pragma unroll
            for (int np = 0; np < 2; np++)
                ldsm_x4(bh[np], sB + (boff[np] ^ kx));
#pragma unroll
            for (int mt = 0; mt < 4; mt++) {
                uint32_t ah[4];
                ldsm_x4(ah, sA + (aoff[mt] ^ kx));
#pragma unroll
                for (int nt = 0; nt < 4; nt++)
                    mma_f16(acc[mt][nt], ah, &bh[nt >> 1][(nt & 1) * 2]);
            }
        }
        __syncthreads();
    }

    int g = lane >> 2, tg = lane & 3;
#pragma unroll
    for (int mt = 0; mt < 4; mt++) {
#pragma unroll
        for (int half = 0; half < 2; half++) {
            int row = m0 + wr * 64 + mt * 16 + g + half * 8;
            const float* rp = nullptr;
            if (res0) rp = ((row < split) ? res0 : res1) + (size_t)row * N;
#pragma unroll
            for (int nt = 0; nt < 4; nt++) {
                int col = n0 + wc * 32 + nt * 8 + tg * 2;
                float vx = acc[mt][nt][half * 2 + 0] * WSCALE_INV;
                float vy = acc[mt][nt][half * 2 + 1] * WSCALE_INV;
                if (bias) { vx += bias[col]; vy += bias[col + 1]; }
                if (Ch) {
                    *(__half2*)(Ch + (size_t)row * N + col) = __floats2half2_rn(vx, vy);
                } else {
                    if (rp) { vx += rp[col]; vy += rp[col + 1]; }
                    *(float2*)(C + (size_t)row * N + col) = make_float2(vx, vy);
                }
            }
        }
    }
}

// ---------------- fp16 flash attention, BQ=128, 4 warps x 32 q-rows -----------------
// K/V fragments loaded once per warp per tile, reused across 2 m-fragments.
// mode 0: write fp32 O; 1: read fp32 O, add, write fp16; 2: write fp16.
static const int ATTN_SMEM = 2 * 2 * 8192;    // 32768

__global__ void __launch_bounds__(128)
attn_mma(const __half* __restrict__ Q, const __half* __restrict__ K,
         const __half* __restrict__ V, int ldv,
         float* __restrict__ O, __half* __restrict__ Oh,
         int LK, int causal, int mode) {
    extern __shared__ char smema[];
    uint32_t sb = smem_to_u32(smema);

    int tid = threadIdx.x;
    int wid = tid >> 5, lane = tid & 31;
    int g = lane >> 2, tg = lane & 3;
    int lr = lane & 7, qlo = (lane >> 3) & 1, qhi = lane >> 4;
    int q0 = blockIdx.x * 128;
    int h  = blockIdx.y;

    // ---- stage Q (128 rows x 128B = 16KB in stage-0), extract 2 m-frag sets ----
#pragma unroll
    for (int it = 0; it < 8; it++) {
        int e = tid + it * 128;           // 0..1023
        int row = e >> 3, q = e & 7;
        uint32_t off = (uint32_t)(row * 128) + (uint32_t)((q * 16) ^ ((row & 7) * 16));
        *(uint4*)(smema + off) = *(const uint4*)(Q + (size_t)(q0 + row) * DM + h * HDIM + q * 8);
    }
    __syncthreads();
    uint32_t qf[2][4][4];
#pragma unroll
    for (int mt = 0; mt < 2; mt++) {
        int arow = wid * 32 + mt * 16 + qlo * 8 + lr;
        uint32_t abase = (uint32_t)(arow * 128) + (uint32_t)((qhi * 16) ^ ((arow & 7) * 16));
#pragma unroll
        for (int ks = 0; ks < 4; ks++)
            ldsm_x4(qf[mt][ks], sb + (abase ^ (uint32_t)(ks << 5)));
    }
    __syncthreads();

    auto issue = [&](int st, int k0) {
        uint32_t base = sb + (uint32_t)st * 16384;
#pragma unroll
        for (int it = 0; it < 4; it++) {
            int e = tid + it * 128;       // 0..511
            int row = e >> 3, q = e & 7;
            uint32_t off = (uint32_t)(row * 128) + (uint32_t)((q * 16) ^ ((row & 7) * 16));
            cp16(base + off,        K + (size_t)(k0 + row) * DM + h * HDIM + q * 8);
            cp16(base + 8192 + off, V + (size_t)(k0 + row) * ldv + h * HDIM + q * 8);
        }
        cp_commit();
    };

    float o[2][8][4] = {};
    float mreg[2][2], lreg[2][2];
#pragma unroll
    for (int mt = 0; mt < 2; mt++) {
        mreg[mt][0] = -1e30f; mreg[mt][1] = -1e30f;
        lreg[mt][0] = 0.f;    lreg[mt][1] = 0.f;
    }

    int ntiles = causal ? (2 * (int)blockIdx.x + 2) : (LK >> 6);
    issue(0, 0);
    for (int kt = 0; kt < ntiles; kt++) {
        int k0 = kt << 6;
        int st = kt & 1;
        if (kt + 1 < ntiles) { issue(st ^ 1, (kt + 1) << 6); cp_wait<1>(); }
        else                 { cp_wait<0>(); }
        __syncthreads();

        uint32_t sK = sb + (uint32_t)st * 16384;
        uint32_t sV = sK + 8192;

        // ---- S = Q K^T : K fragments loaded once, used for both m-frags ----
        float s[2][8][4] = {};
#pragma unroll
        for (int ks = 0; ks < 4; ks++) {
            uint32_t kx = (uint32_t)(ks << 5);
            uint32_t bf[4][4];
#pragma unroll
            for (int np = 0; np < 4; np++) {
                int br = np * 16 + qhi * 8 + lr;
                uint32_t boff = (uint32_t)(br * 128) +
                                (uint32_t)(((qlo * 16) ^ (int)kx) ^ ((br & 7) * 16));
                ldsm_x4(bf[np], sK + boff);
            }
#pragma unroll
            for (int mt = 0; mt < 2; mt++)
#pragma unroll
                for (int nt = 0; nt < 8; nt++)
                    mma_f16(s[mt][nt], qf[mt][ks], &bf[nt >> 1][(nt & 1) * 2]);
        }

        // ---- causal mask (near-diagonal tiles) ----
        if (causal) {
#pragma unroll
            for (int mt = 0; mt < 2; mt++) {
                int rbase = q0 + wid * 32 + mt * 16;
                if (k0 + 63 > rbase) {
                    int r0 = rbase + g, r1 = r0 + 8;
#pragma unroll
                    for (int nt = 0; nt < 8; nt++) {
                        int kbase = k0 + nt * 8 + tg * 2;
                        if (kbase > r0)     s[mt][nt][0] = -1e30f;
                        if (kbase + 1 > r0) s[mt][nt][1] = -1e30f;
                        if (kbase > r1)     s[mt][nt][2] = -1e30f;
                        if (kbase + 1 > r1) s[mt][nt][3] = -1e30f;
                    }
                }
            }
        }

        // ---- online softmax (per m-frag) ----
#pragma unroll
        for (int mt = 0; mt < 2; mt++) {
            float mx0 = -1e30f, mx1 = -1e30f;
#pragma unroll
            for (int nt = 0; nt < 8; nt++) {
                mx0 = fmaxf(mx0, fmaxf(s[mt][nt][0], s[mt][nt][1]));
                mx1 = fmaxf(mx1, fmaxf(s[mt][nt][2], s[mt][nt][3]));
            }
            mx0 = fmaxf(mx0, __shfl_xor_sync(0xffffffffu, mx0, 1));
            mx0 = fmaxf(mx0, __shfl_xor_sync(0xffffffffu, mx0, 2));
            mx1 = fmaxf(mx1, __shfl_xor_sync(0xffffffffu, mx1, 1));
            mx1 = fmaxf(mx1, __shfl_xor_sync(0xffffffffu, mx1, 2));
            float mn0 = fmaxf(mreg[mt][0], mx0), mn1 = fmaxf(mreg[mt][1], mx1);
            float al0 = fexp(mreg[mt][0] - mn0), al1 = fexp(mreg[mt][1] - mn1);
            float sum0 = 0.f, sum1 = 0.f;
#pragma unroll
            for (int nt = 0; nt < 8; nt++) {
                s[mt][nt][0] = fexp(s[mt][nt][0] - mn0);
                s[mt][nt][1] = fexp(s[mt][nt][1] - mn0);
                s[mt][nt][2] = fexp(s[mt][nt][2] - mn1);
                s[mt][nt][3] = fexp(s[mt][nt][3] - mn1);
                sum0 += s[mt][nt][0] + s[mt][nt][1];
                sum1 += s[mt][nt][2] + s[mt][nt][3];
            }
            sum0 += __shfl_xor_sync(0xffffffffu, sum0, 1);
            sum0 += __shfl_xor_sync(0xffffffffu, sum0, 2);
            sum1 += __shfl_xor_sync(0xffffffffu, sum1, 1);
            sum1 += __shfl_xor_sync(0xffffffffu, sum1, 2);
            lreg[mt][0] = lreg[mt][0] * al0 + sum0; mreg[mt][0] = mn0;
            lreg[mt][1] = lreg[mt][1] * al1 + sum1; mreg[mt][1] = mn1;
#pragma unroll
            for (int nt = 0; nt < 8; nt++) {
                o[mt][nt][0] *= al0; o[mt][nt][1] *= al0;
                o[mt][nt][2] *= al1; o[mt][nt][3] *= al1;
            }
        }

        // ---- O += P V : V fragments loaded once per kb, used for both m-frags ----
#pragma unroll
        for (int kb = 0; kb < 4; kb++) {
            uint32_t vf[4][4];
            int vr = kb * 16 + qlo * 8 + lr;
            uint32_t vrow = (uint32_t)(vr * 128);
            uint32_t vsw  = (uint32_t)((vr & 7) * 16);
#pragma unroll
            for (int np = 0; np < 4; np++)
                ldsm_x4_t(vf[np], sV + vrow + (((uint32_t)(np * 32 + qhi * 16)) ^ vsw));
#pragma unroll
            for (int mt = 0; mt < 2; mt++) {
                uint32_t ph[4];
                __half2 p0 = __floats2half2_rn(s[mt][2 * kb][0],     s[mt][2 * kb][1]);
                __half2 p1 = __floats2half2_rn(s[mt][2 * kb][2],     s[mt][2 * kb][3]);
                __half2 p2 = __floats2half2_rn(s[mt][2 * kb + 1][0], s[mt][2 * kb + 1][1]);
                __half2 p3 = __floats2half2_rn(s[mt][2 * kb + 1][2], s[mt][2 * kb + 1][3]);
                ph[0] = *(uint32_t*)&p0; ph[1] = *(uint32_t*)&p1;
                ph[2] = *(uint32_t*)&p2; ph[3] = *(uint32_t*)&p3;
#pragma unroll
                for (int nt = 0; nt < 8; nt++)
                    mma_f16(o[mt][nt], ph, &vf[nt >> 1][(nt & 1) * 2]);
            }
        }
        __syncthreads();
    }

    // ---- epilogue ----
#pragma unroll
    for (int mt = 0; mt < 2; mt++) {
        float inv0 = 1.f / lreg[mt][0], inv1 = 1.f / lreg[mt][1];
        int row0 = q0 + wid * 32 + mt * 16 + g;
        int row1 = row0 + 8;
#pragma unroll
        for (int nt = 0; nt < 8; nt++) {
            int col = h * HDIM + nt * 8 + tg * 2;
            float v00 = o[mt][nt][0] * inv0, v01 = o[mt][nt][1] * inv0;
            float v10 = o[mt][nt][2] * inv1, v11 = o[mt][nt][3] * inv1;
            if (mode == 0) {
                *(float2*)(O + (size_t)row0 * DM + col) = make_float2(v00, v01);
                *(float2*)(O + (size_t)row1 * DM + col) = make_float2(v10, v11);
            } else {
                if (mode == 1) {
                    float2 a0 = *(float2*)(O + (size_t)row0 * DM + col);
                    float2 a1 = *(float2*)(O + (size_t)row1 * DM + col);
                    v00 += a0.x; v01 += a0.y; v10 += a1.x; v11 += a1.y;
                }
                *(__half2*)(Oh + (size_t)row0 * DM + col) = __floats2half2_rn(v00, v01);
                *(__half2*)(Oh + (size_t)row1 * DM + col) = __floats2half2_rn(v10, v11);
            }
        }
    }
}

// ---------------- host orchestration ----------------------------------------------
extern "C" void kernel_launch(void* const* d_in, const int* in_sizes, int n_in,
                              void* d_out, int out_size) {
    const float* x     = (const float*)d_in[0];
    const float* ctx   = (const float*)d_in[1];
    const float* qkv_w = (const float*)d_in[2];
    const float* qkv_b = (const float*)d_in[3];
    const float* out_w = (const float*)d_in[4];
    const float* out_b = (const float*)d_in[5];
    const float* w1    = (const float*)d_in[6];
    const float* w3    = (const float*)d_in[7];
    const float* w2    = (const float*)d_in[8];
    const float* n1g   = (const float*)d_in[9];
    const float* n1b   = (const float*)d_in[10];
    const float* n2g   = (const float*)d_in[11];
    const float* n2b   = (const float*)d_in[12];
    float* out = (float*)d_out;

    cudaFuncSetAttribute(mma_gemm_kernel, cudaFuncAttributeMaxDynamicSharedMemorySize, GEMM_SMEM);
    cudaFuncSetAttribute(attn_mma, cudaFuncAttributeMaxDynamicSharedMemorySize, ATTN_SMEM);

    void* p;
    cudaGetSymbolAddress(&p, g_attn);   float* attn   = (float*)p;
    cudaGetSymbolAddress(&p, g_h1);     float* h1     = (float*)p;
    cudaGetSymbolAddress(&p, g_qkv_h);  __half* qkvh  = (__half*)p;
    cudaGetSymbolAddress(&p, g_gateup); __half* gateup = (__half*)p;
    cudaGetSymbolAddress(&p, g_act_h);  __half* ah    = (__half*)p;
    cudaGetSymbolAddress(&p, g_wqkv);   __half* wq  = (__half*)p;
    cudaGetSymbolAddress(&p, g_wout);   __half* wo  = (__half*)p;
    cudaGetSymbolAddress(&p, g_w13);    __half* w13 = (__half*)p;
    cudaGetSymbolAddress(&p, g_w2);     __half* w2p = (__half*)p;
    cudaGetSymbolAddress(&p, g_qx);     __half* qx  = (__half*)p;
    cudaGetSymbolAddress(&p, g_qs);     __half* qs  = (__half*)p;
    cudaGetSymbolAddress(&p, g_kx);     __half* kx  = (__half*)p;
    cudaGetSymbolAddress(&p, g_kc);     __half* kc  = (__half*)p;

    dim3 tb(32, 8);
    build_rope_table<<<(MAXPOS * 32 + 255) / 256, 256>>>();

    // weight transpose + single fp16 (pre-scaled); w1,w3 packed [5632][1024]
    wt_f16_kernel<<<dim3(3 * DM / 32, DM / 32), tb>>>(qkv_w, wq, DM, 3 * DM);
    wt_f16_kernel<<<dim3(DM / 32, DM / 32),     tb>>>(out_w, wo, DM, DM);
    wt_f16_kernel<<<dim3(HID / 32, DM / 32),    tb>>>(w1, w13, DM, HID);
    wt_f16_kernel<<<dim3(HID / 32, DM / 32),    tb>>>(w3, w13 + (size_t)HID * DM, DM, HID);
    wt_f16_kernel<<<dim3(DM / 32, HID / 32),    tb>>>(w2, w2p, HID, DM);

    // LN1 -> fp16 A buffer [LTOT][DM]
    ln_f16_kernel<<<LXX, 256>>>(x,   ah,                    n1g, n1b);
    ln_f16_kernel<<<LCC, 256>>>(ctx, ah + (size_t)LXX * DM, n1g, n1b);

    // QKV projection (fp16 out, bias)
    mma_gemm_kernel<<<dim3(3 * DM / 128, LTOT / 128), 256, GEMM_SMEM>>>(
        ah, wq, nullptr, qkvh, qkv_b, nullptr, nullptr, 0, LTOT, 3 * DM, DM);

    // RoPE: Q (QSCALE) and K (1.0) to contiguous fp16; V stays in qkvh (strided)
    rope_f16_kernel<<<(LXX * 512 + 255) / 256, 256>>>(qkvh, 3 * DM, qx, LXX, POS_X, QSCALE);
    rope_f16_kernel<<<(2048 * 512 + 255) / 256, 256>>>(qkvh + (size_t)(LXX + HWSP) * 3 * DM, 3 * DM, qs, 2048, HWSP, QSCALE);
    rope_f16_kernel<<<(LXX * 512 + 255) / 256, 256>>>(qkvh + DM, 3 * DM, kx, LXX, POS_X, 1.f);
    rope_f16_kernel<<<(LCC * 512 + 255) / 256, 256>>>(qkvh + (size_t)LXX * 3 * DM + DM, 3 * DM, kc, LCC, POS_C, 1.f);

    const __half* vx = qkvh + 2 * DM;                          // rows 0..2047 (strided)
    const __half* vc = qkvh + (size_t)LXX * 3 * DM + 2 * DM;   // rows 2048..6143 (strided)

    // a1 (mode 0: fp32 staging) ; a2 (mode 1: +a1 -> fp16) ; a3 (mode 2: fp16)
    attn_mma<<<dim3(LXX / 128, NH), 128, ATTN_SMEM>>>(qx, kc, vc, 3 * DM,
        attn, nullptr, LCC, 0, 0);
    attn_mma<<<dim3(LXX / 128, NH), 128, ATTN_SMEM>>>(qx, kx, vx, 3 * DM,
        attn, ah, LXX, 1, 1);
    attn_mma<<<dim3(2048 / 128, NH), 128, ATTN_SMEM>>>(qs, kc, vc, 3 * DM,
        nullptr, ah + (size_t)2048 * DM, LCC, 0, 2);

    // out projection + bias + residual -> h1 (fp32)
    mma_gemm_kernel<<<dim3(DM / 128, LOUT / 128), 256, GEMM_SMEM>>>(
        ah, wo, h1, nullptr, out_b, x, ctx, 2048, LOUT, DM, DM);

    // LN2 -> fp16
    ln_f16_kernel<<<LOUT, 256>>>(h1, ah, n2g, n2b);

    // FFN: combined w1|w3 GEMM -> gateup (fp16), fused silu*mul -> fp16, w2 GEMM
    mma_gemm_kernel<<<dim3(2 * HID / 128, LOUT / 128), 256, GEMM_SMEM>>>(
        ah, w13, nullptr, gateup, nullptr, nullptr, nullptr, 0, LOUT, 2 * HID, DM);
    silu_mul_f16_kernel<<<dim3(HID / 256, LOUT), 256>>>(gateup, ah);
    mma_gemm_kernel<<<dim3(DM / 128, LOUT / 128), 256, GEMM_SMEM>>>(
        ah, w2p, out, nullptr, nullptr, h1, h1, LOUT, LOUT, DM, HID);
}

// round 15
// speedup vs baseline: 1.0786x; 1.0007x over previous
#include <cuda_runtime.h>
#include <cuda_fp16.h>
#include <math.h>
#include <stdint.h>

// ---------------- problem constants (from setup_inputs, deterministic) ----------
#define LXX     2048
#define LCC     4096
#define DM      1024
#define NH      16
#define HDIM    64
#define HID     2816
#define LTOT    6144
#define LOUT    4096
#define POS_X   4096
#define POS_C   0
#define HWSP    2048
#define MAXPOS  6144

#define WSCALE     64.0f
#define WSCALE_INV 0.015625f
#define QSCALE     0.125f

// ---------------- scratch (device globals; no runtime allocation) ---------------
__device__ float  g_attn  [LXX * DM];          // a1 fp32 staging
__device__ float  g_h1    [LOUT * DM];
__device__ float  g_cos   [MAXPOS * 32];
__device__ float  g_sin   [MAXPOS * 32];

__device__ __half g_qkv_h [LTOT * 3 * DM];     // QKV projection, fp16
__device__ __half g_gateup[LOUT * 2 * HID];    // FFN1 output, fp16
__device__ __half g_act_h [LOUT * HID];        // A operand of weight GEMMs

// single fp16 weights [N][K], pre-scaled by WSCALE
__device__ __half g_wqkv[3 * DM * DM];
__device__ __half g_wout[DM * DM];
__device__ __half g_w13 [2 * HID * DM];
__device__ __half g_w2  [DM * HID];

// fp16 attention operands (Q pre-scaled by QSCALE)
__device__ __half g_q13[LOUT * DM];            // rows 0..2047: qx ; rows 2048..4095: qs
__device__ __half g_kx [LXX * DM];
__device__ __half g_kc [LCC * DM];

// ---------------- helpers (portable: sm_80+ PTX) ----------------------------------
__device__ __forceinline__ uint32_t smem_to_u32(const void* p) {
    uint32_t a;
    asm("{ .reg .u64 t; cvta.to.shared.u64 t, %1; cvt.u32.u64 %0, t; }" : "=r"(a) : "l"(p));
    return a;
}
#define SMEM_SWIZZLE_128B(b) ((b) ^ (((b) >> 3) & 0x70))

__device__ __forceinline__ void cp16(uint32_t s, const void* g) {
    asm volatile("cp.async.cg.shared.global [%0], [%1], 16;" :: "r"(s), "l"(g) : "memory");
}
__device__ __forceinline__ void cp_commit() {
    asm volatile("cp.async.commit_group;" ::: "memory");
}
template<int N> __device__ __forceinline__ void cp_wait() {
    asm volatile("cp.async.wait_group %0;" :: "n"(N) : "memory");
}

__device__ __forceinline__ void ldsm_x4(uint32_t* r, uint32_t addr) {
    asm volatile("ldmatrix.sync.aligned.m8n8.x4.shared.b16 {%0,%1,%2,%3}, [%4];"
        : "=r"(r[0]), "=r"(r[1]), "=r"(r[2]), "=r"(r[3]) : "r"(addr));
}
__device__ __forceinline__ void ldsm_x4_t(uint32_t* r, uint32_t addr) {
    asm volatile("ldmatrix.sync.aligned.m8n8.x4.trans.shared.b16 {%0,%1,%2,%3}, [%4];"
        : "=r"(r[0]), "=r"(r[1]), "=r"(r[2]), "=r"(r[3]) : "r"(addr));
}
__device__ __forceinline__ void mma_f16(float* c, const uint32_t* a, const uint32_t* b) {
    asm volatile("mma.sync.aligned.m16n8k16.row.col.f32.f16.f16.f32 "
        "{%0,%1,%2,%3}, {%4,%5,%6,%7}, {%8,%9}, {%0,%1,%2,%3};"
        : "+f"(c[0]), "+f"(c[1]), "+f"(c[2]), "+f"(c[3])
        : "r"(a[0]), "r"(a[1]), "r"(a[2]), "r"(a[3]), "r"(b[0]), "r"(b[1]));
}

// fast exp on FMA pipe (x <= 0), rel err ~2e-6
__device__ __forceinline__ float fexp(float x) {
    x = fmaxf(x, -87.0f);
    float t = x * 1.4426950408889634f;
    float r = t + 12582912.0f;
    float n = r - 12582912.0f;
    float f = t - n;
    float p = 0.0013298820f;
    p = fmaf(p, f, 0.0096181291f);
    p = fmaf(p, f, 0.0555041087f);
    p = fmaf(p, f, 0.2402265069f);
    p = fmaf(p, f, 0.6931471806f);
    p = fmaf(p, f, 1.0f);
    int ni = (int)n;
    return p * __int_as_float((ni + 127) << 23);
}

// ---------------- rope cos/sin table (fp64 angles) -------------------------------
__global__ void build_rope_table() {
    int idx = blockIdx.x * blockDim.x + threadIdx.x;
    if (idx >= MAXPOS * 32) return;
    int pos = idx >> 5, j = idx & 31;
    double inv = pow(10000.0, -((double)(2 * j)) / 64.0);
    double ang = (double)pos * inv;
    g_cos[idx] = (float)cos(ang);
    g_sin[idx] = (float)sin(ang);
}

// ---------------- LayerNorm fused with fp16 output ---------------------------------
__global__ void ln_f16_kernel(const float* __restrict__ in,
                              __half* __restrict__ out,
                              const float* __restrict__ gam,
                              const float* __restrict__ bet) {
    __shared__ float sh[32];
    __shared__ float s_mean, s_rstd;
    int row = blockIdx.x, t = threadIdx.x;
    const float* x = in + (size_t)row * DM;
    float v[4];
    float s = 0.f;
#pragma unroll
    for (int i = 0; i < 4; i++) { v[i] = x[t + 256 * i]; s += v[i]; }
#pragma unroll
    for (int o = 16; o; o >>= 1) s += __shfl_xor_sync(0xffffffffu, s, o);
    if ((t & 31) == 0) sh[t >> 5] = s;
    __syncthreads();
    if (t < 32) {
        float z = (t < 8) ? sh[t] : 0.f;
#pragma unroll
        for (int o = 4; o; o >>= 1) z += __shfl_xor_sync(0xffffffffu, z, o);
        if (t == 0) s_mean = z * (1.f / 1024.f);
    }
    __syncthreads();
    float mean = s_mean;
    float q = 0.f;
#pragma unroll
    for (int i = 0; i < 4; i++) { float d = v[i] - mean; q += d * d; }
#pragma unroll
    for (int o = 16; o; o >>= 1) q += __shfl_xor_sync(0xffffffffu, q, o);
    if ((t & 31) == 0) sh[t >> 5] = q;
    __syncthreads();
    if (t < 32) {
        float z = (t < 8) ? sh[t] : 0.f;
#pragma unroll
        for (int o = 4; o; o >>= 1) z += __shfl_xor_sync(0xffffffffu, z, o);
        if (t == 0) s_rstd = rsqrtf(z * (1.f / 1024.f) + 1e-5f);
    }
    __syncthreads();
    float rstd = s_rstd;
#pragma unroll
    for (int i = 0; i < 4; i++) {
        int c = t + 256 * i;
        float r = (v[i] - mean) * rstd * gam[c] + bet[c];
        out[(size_t)row * DM + c] = __float2half(r);
    }
}

// ---------------- RoPE: fp16 strided in -> fp16 contiguous out ---------------------
__global__ void rope_f16_kernel(const __half* __restrict__ src, int lds,
                                __half* __restrict__ out,
                                int L, int pos0, float scale) {
    int idx = blockIdx.x * blockDim.x + threadIdx.x;
    if (idx >= L * 512) return;
    int j = idx & 31, h = (idx >> 5) & 15, l = idx >> 9;
    int pos = pos0 + l;
    float c = g_cos[pos * 32 + j], s = g_sin[pos * 32 + j];
    const __half* p = src + (size_t)l * lds + h * HDIM;
    float t1 = __half2float(p[j]), t2 = __half2float(p[j + 32]);
    size_t o = (size_t)l * DM + h * HDIM;
    out[o + j]      = __float2half((t1 * c - t2 * s) * scale);
    out[o + j + 32] = __float2half((t2 * c + t1 * s) * scale);
}

// ---------------- weight transpose + single fp16 (pre-scaled by WSCALE) ------------
__global__ void wt_f16_kernel(const float* __restrict__ w,
                              __half* __restrict__ o, int K, int N) {
    __shared__ float t[32][33];
    int n0 = blockIdx.x * 32, k0 = blockIdx.y * 32;
    int tx = threadIdx.x, ty = threadIdx.y;
#pragma unroll
    for (int i = 0; i < 32; i += 8)
        t[ty + i][tx] = w[(size_t)(k0 + ty + i) * N + n0 + tx];
    __syncthreads();
#pragma unroll
    for (int i = 0; i < 32; i += 8) {
        int n = n0 + ty + i, k = k0 + tx;
        o[(size_t)n * K + k] = __float2half(t[tx][ty + i] * WSCALE);
    }
}

// ---------------- silu(g)*u (fp16 in) fused with fp16 output ------------------------
__global__ void silu_mul_f16_kernel(const __half* __restrict__ gu,
                                    __half* __restrict__ out) {
    int col = blockIdx.x * 256 + threadIdx.x;     // < HID (11 blocks x 256 = 2816)
    int row = blockIdx.y;
    float g = __half2float(gu[(size_t)row * (2 * HID) + col]);
    float u = __half2float(gu[(size_t)row * (2 * HID) + HID + col]);
    float r = (g / (1.f + __expf(-g))) * u;
    out[(size_t)row * HID + col] = __float2half(r);
}

// ---------------- fp16 single-pass GEMM, cp.async 2-stage pipeline ------------------
// C = (1/WSCALE) * A[M][K] * B[N][K]^T (+bias). Out fp32 (+residual) or fp16 (Ch).
static const int GEMM_SMEM = 2 * 2 * 16384;   // 65536

__global__ void __launch_bounds__(256, 2)
mma_gemm_kernel(const __half* __restrict__ A, const __half* __restrict__ B,
                float* __restrict__ C, __half* __restrict__ Ch,
                const float* __restrict__ bias,
                const float* __restrict__ res0, const float* __restrict__ res1, int split,
                int M, int N, int K) {
    extern __shared__ char smem[];
    uint32_t sbase = smem_to_u32(smem);

    int tid = threadIdx.x;
    int wid = tid >> 5, lane = tid & 31;
    int wr = wid >> 2, wc = wid & 3;
    int m0 = blockIdx.y * 128, n0 = blockIdx.x * 128;

    int lr  = lane & 7;
    int lq  = lane >> 3;
    int qlo = lq & 1, qhi = lq >> 1;

    uint32_t aoff[4];
#pragma unroll
    for (int mt = 0; mt < 4; mt++) {
        int row = wr * 64 + mt * 16 + qlo * 8 + lr;
        aoff[mt] = (uint32_t)(row * 128) + (uint32_t)((qhi * 16) ^ ((row & 7) * 16));
    }
    uint32_t boff[2];
#pragma unroll
    for (int np = 0; np < 2; np++) {
        int row = wc * 32 + np * 16 + qhi * 8 + lr;
        boff[np] = (uint32_t)(row * 128) + (uint32_t)((qlo * 16) ^ ((row & 7) * 16));
    }

    auto issue = [&](int st, int kc0) {
        uint32_t base = sbase + (uint32_t)st * 32768;
#pragma unroll
        for (int it = 0; it < 4; it++) {
            int idx = tid + it * 256;
            int r = idx >> 3, q = idx & 7;
            uint32_t so = SMEM_SWIZZLE_128B((uint32_t)(r * 128 + q * 16));
            cp16(base + so,         A + (size_t)(m0 + r) * K + kc0 + q * 8);
            cp16(base + 16384 + so, B + (size_t)(n0 + r) * K + kc0 + q * 8);
        }
        cp_commit();
    };

    float acc[4][4][4] = {};
    int nchunks = K >> 6;

    issue(0, 0);
    for (int kc = 0; kc < nchunks; kc++) {
        int st = kc & 1;
        if (kc + 1 < nchunks) { issue(st ^ 1, (kc + 1) << 6); cp_wait<1>(); }
        else                  { cp_wait<0>(); }
        __syncthreads();

        uint32_t sA = sbase + (uint32_t)st * 32768;
        uint32_t sB = sA + 16384;

#pragma unroll
        for (int ks = 0; ks < 4; ks++) {
            uint32_t kx = (uint32_t)(ks << 5);
            uint32_t bh[2][4];
#pragma unroll
            for (int np = 0; np < 2; np++)
                ldsm_x4(bh[np], sB + (boff[np] ^ kx));
#pragma unroll
            for (int mt = 0; mt < 4; mt++) {
                uint32_t ah[4];
                ldsm_x4(ah, sA + (aoff[mt] ^ kx));
#pragma unroll
                for (int nt = 0; nt < 4; nt++)
                    mma_f16(acc[mt][nt], ah, &bh[nt >> 1][(nt & 1) * 2]);
            }
        }
        __syncthreads();
    }

    int g = lane >> 2, tg = lane & 3;
#pragma unroll
    for (int mt = 0; mt < 4; mt++) {
#pragma unroll
        for (int half = 0; half < 2; half++) {
            int row = m0 + wr * 64 + mt * 16 + g + half * 8;
            const float* rp = nullptr;
            if (res0) rp = ((row < split) ? res0 : res1) + (size_t)row * N;
#pragma unroll
            for (int nt = 0; nt < 4; nt++) {
                int col = n0 + wc * 32 + nt * 8 + tg * 2;
                float vx = acc[mt][nt][half * 2 + 0] * WSCALE_INV;
                float vy = acc[mt][nt][half * 2 + 1] * WSCALE_INV;
                if (bias) { vx += bias[col]; vy += bias[col + 1]; }
                if (Ch) {
                    *(__half2*)(Ch + (size_t)row * N + col) = __floats2half2_rn(vx, vy);
                } else {
                    if (rp) { vx += rp[col]; vy += rp[col + 1]; }
                    *(float2*)(C + (size_t)row * N + col) = make_float2(vx, vy);
                }
            }
        }
    }
}

// ---------------- fp16 flash attention, BQ=128, 4 warps x 32 q-rows -----------------
// mode 0: write fp32 O; 1: read fp32 O, add, write fp16; 2: write fp16;
// mode 3: merged a1|a3 — q0 < 2048 -> fp32 O, else fp16 Oh (row-indexed directly).
static const int ATTN_SMEM = 2 * 2 * 8192;    // 32768

__global__ void __launch_bounds__(128)
attn_mma(const __half* __restrict__ Q, const __half* __restrict__ K,
         const __half* __restrict__ V, int ldv,
         float* __restrict__ O, __half* __restrict__ Oh,
         int LK, int causal, int mode) {
    extern __shared__ char smema[];
    uint32_t sb = smem_to_u32(smema);

    int tid = threadIdx.x;
    int wid = tid >> 5, lane = tid & 31;
    int g = lane >> 2, tg = lane & 3;
    int lr = lane & 7, qlo = (lane >> 3) & 1, qhi = lane >> 4;
    int q0 = blockIdx.x * 128;
    int h  = blockIdx.y;

    // ---- stage Q (128 rows x 128B = 16KB in stage-0), extract 2 m-frag sets ----
#pragma unroll
    for (int it = 0; it < 8; it++) {
        int e = tid + it * 128;           // 0..1023
        int row = e >> 3, q = e & 7;
        uint32_t off = (uint32_t)(row * 128) + (uint32_t)((q * 16) ^ ((row & 7) * 16));
        *(uint4*)(smema + off) = *(const uint4*)(Q + (size_t)(q0 + row) * DM + h * HDIM + q * 8);
    }
    __syncthreads();
    uint32_t qf[2][4][4];
#pragma unroll
    for (int mt = 0; mt < 2; mt++) {
        int arow = wid * 32 + mt * 16 + qlo * 8 + lr;
        uint32_t abase = (uint32_t)(arow * 128) + (uint32_t)((qhi * 16) ^ ((arow & 7) * 16));
#pragma unroll
        for (int ks = 0; ks < 4; ks++)
            ldsm_x4(qf[mt][ks], sb + (abase ^ (uint32_t)(ks << 5)));
    }
    __syncthreads();

    auto issue = [&](int st, int k0) {
        uint32_t base = sb + (uint32_t)st * 16384;
#pragma unroll
        for (int it = 0; it < 4; it++) {
            int e = tid + it * 128;       // 0..511
            int row = e >> 3, q = e & 7;
            uint32_t off = (uint32_t)(row * 128) + (uint32_t)((q * 16) ^ ((row & 7) * 16));
            cp16(base + off,        K + (size_t)(k0 + row) * DM + h * HDIM + q * 8);
            cp16(base + 8192 + off, V + (size_t)(k0 + row) * ldv + h * HDIM + q * 8);
        }
        cp_commit();
    };

    float o[2][8][4] = {};
    float mreg[2][2], lreg[2][2];
#pragma unroll
    for (int mt = 0; mt < 2; mt++) {
        mreg[mt][0] = -1e30f; mreg[mt][1] = -1e30f;
        lreg[mt][0] = 0.f;    lreg[mt][1] = 0.f;
    }

    int ntiles = causal ? (2 * (int)blockIdx.x + 2) : (LK >> 6);
    issue(0, 0);
    for (int kt = 0; kt < ntiles; kt++) {
        int k0 = kt << 6;
        int st = kt & 1;
        if (kt + 1 < ntiles) { issue(st ^ 1, (kt + 1) << 6); cp_wait<1>(); }
        else                 { cp_wait<0>(); }
        __syncthreads();

        uint32_t sK = sb + (uint32_t)st * 16384;
        uint32_t sV = sK + 8192;

        // ---- S = Q K^T : K fragments loaded once, used for both m-frags ----
        float s[2][8][4] = {};
#pragma unroll
        for (int ks = 0; ks < 4; ks++) {
            uint32_t kx = (uint32_t)(ks << 5);
            uint32_t bf[4][4];
#pragma unroll
            for (int np = 0; np < 4; np++) {
                int br = np * 16 + qhi * 8 + lr;
                uint32_t boff = (uint32_t)(br * 128) +
                                (uint32_t)(((qlo * 16) ^ (int)kx) ^ ((br & 7) * 16));
                ldsm_x4(bf[np], sK + boff);
            }
#pragma unroll
            for (int mt = 0; mt < 2; mt++)
#pragma unroll
                for (int nt = 0; nt < 8; nt++)
                    mma_f16(s[mt][nt], qf[mt][ks], &bf[nt >> 1][(nt & 1) * 2]);
        }

        // ---- causal mask (near-diagonal tiles) ----
        if (causal) {
#pragma unroll
            for (int mt = 0; mt < 2; mt++) {
                int rbase = q0 + wid * 32 + mt * 16;
                if (k0 + 63 > rbase) {
                    int r0 = rbase + g, r1 = r0 + 8;
#pragma unroll
                    for (int nt = 0; nt < 8; nt++) {
                        int kbase = k0 + nt * 8 + tg * 2;
                        if (kbase > r0)     s[mt][nt][0] = -1e30f;
                        if (kbase + 1 > r0) s[mt][nt][1] = -1e30f;
                        if (kbase > r1)     s[mt][nt][2] = -1e30f;
                        if (kbase + 1 > r1) s[mt][nt][3] = -1e30f;
                    }
                }
            }
        }

        // ---- online softmax (per m-frag) ----
#pragma unroll
        for (int mt = 0; mt < 2; mt++) {
            float mx0 = -1e30f, mx1 = -1e30f;
#pragma unroll
            for (int nt = 0; nt < 8; nt++) {
                mx0 = fmaxf(mx0, fmaxf(s[mt][nt][0], s[mt][nt][1]));
                mx1 = fmaxf(mx1, fmaxf(s[mt][nt][2], s[mt][nt][3]));
            }
            mx0 = fmaxf(mx0, __shfl_xor_sync(0xffffffffu, mx0, 1));
            mx0 = fmaxf(mx0, __shfl_xor_sync(0xffffffffu, mx0, 2));
            mx1 = fmaxf(mx1, __shfl_xor_sync(0xffffffffu, mx1, 1));
            mx1 = fmaxf(mx1, __shfl_xor_sync(0xffffffffu, mx1, 2));
            float mn0 = fmaxf(mreg[mt][0], mx0), mn1 = fmaxf(mreg[mt][1], mx1);
            float al0 = fexp(mreg[mt][0] - mn0), al1 = fexp(mreg[mt][1] - mn1);
            float sum0 = 0.f, sum1 = 0.f;
#pragma unroll
            for (int nt = 0; nt < 8; nt++) {
                s[mt][nt][0] = fexp(s[mt][nt][0] - mn0);
                s[mt][nt][1] = fexp(s[mt][nt][1] - mn0);
                s[mt][nt][2] = fexp(s[mt][nt][2] - mn1);
                s[mt][nt][3] = fexp(s[mt][nt][3] - mn1);
                sum0 += s[mt][nt][0] + s[mt][nt][1];
                sum1 += s[mt][nt][2] + s[mt][nt][3];
            }
            sum0 += __shfl_xor_sync(0xffffffffu, sum0, 1);
            sum0 += __shfl_xor_sync(0xffffffffu, sum0, 2);
            sum1 += __shfl_xor_sync(0xffffffffu, sum1, 1);
            sum1 += __shfl_xor_sync(0xffffffffu, sum1, 2);
            lreg[mt][0] = lreg[mt][0] * al0 + sum0; mreg[mt][0] = mn0;
            lreg[mt][1] = lreg[mt][1] * al1 + sum1; mreg[mt][1] = mn1;
#pragma unroll
            for (int nt = 0; nt < 8; nt++) {
                o[mt][nt][0] *= al0; o[mt][nt][1] *= al0;
                o[mt][nt][2] *= al1; o[mt][nt][3] *= al1;
            }
        }

        // ---- O += P V : V fragments loaded once per kb, used for both m-frags ----
#pragma unroll
        for (int kb = 0; kb < 4; kb++) {
            uint32_t vf[4][4];
            int vr = kb * 16 + qlo * 8 + lr;
            uint32_t vrow = (uint32_t)(vr * 128);
            uint32_t vsw  = (uint32_t)((vr & 7) * 16);
#pragma unroll
            for (int np = 0; np < 4; np++)
                ldsm_x4_t(vf[np], sV + vrow + (((uint32_t)(np * 32 + qhi * 16)) ^ vsw));
#pragma unroll
            for (int mt = 0; mt < 2; mt++) {
                uint32_t ph[4];
                __half2 p0 = __floats2half2_rn(s[mt][2 * kb][0],     s[mt][2 * kb][1]);
                __half2 p1 = __floats2half2_rn(s[mt][2 * kb][2],     s[mt][2 * kb][3]);
                __half2 p2 = __floats2half2_rn(s[mt][2 * kb + 1][0], s[mt][2 * kb + 1][1]);
                __half2 p3 = __floats2half2_rn(s[mt][2 * kb + 1][2], s[mt][2 * kb + 1][3]);
                ph[0] = *(uint32_t*)&p0; ph[1] = *(uint32_t*)&p1;
                ph[2] = *(uint32_t*)&p2; ph[3] = *(uint32_t*)&p3;
#pragma unroll
                for (int nt = 0; nt < 8; nt++)
                    mma_f16(o[mt][nt], ph, &vf[nt >> 1][(nt & 1) * 2]);
            }
        }
        __syncthreads();
    }

    // ---- epilogue ----
    int emode = mode;
    if (mode == 3) emode = (q0 < 2048) ? 0 : 2;   // merged a1|a3 select
#pragma unroll
    for (int mt = 0; mt < 2; mt++) {
        float inv0 = 1.f / lreg[mt][0], inv1 = 1.f / lreg[mt][1];
        int row0 = q0 + wid * 32 + mt * 16 + g;
        int row1 = row0 + 8;
#pragma unroll
        for (int nt = 0; nt < 8; nt++) {
            int col = h * HDIM + nt * 8 + tg * 2;
            float v00 = o[mt][nt][0] * inv0, v01 = o[mt][nt][1] * inv0;
            float v10 = o[mt][nt][2] * inv1, v11 = o[mt][nt][3] * inv1;
            if (emode == 0) {
                *(float2*)(O + (size_t)row0 * DM + col) = make_float2(v00, v01);
                *(float2*)(O + (size_t)row1 * DM + col) = make_float2(v10, v11);
            } else {
                if (emode == 1) {
                    float2 a0 = *(float2*)(O + (size_t)row0 * DM + col);
                    float2 a1 = *(float2*)(O + (size_t)row1 * DM + col);
                    v00 += a0.x; v01 += a0.y; v10 += a1.x; v11 += a1.y;
                }
                *(__half2*)(Oh + (size_t)row0 * DM + col) = __floats2half2_rn(v00, v01);
                *(__half2*)(Oh + (size_t)row1 * DM + col) = __floats2half2_rn(v10, v11);
            }
        }
    }
}

// ---------------- host orchestration ----------------------------------------------
extern "C" void kernel_launch(void* const* d_in, const int* in_sizes, int n_in,
                              void* d_out, int out_size) {
    const float* x     = (const float*)d_in[0];
    const float* ctx   = (const float*)d_in[1];
    const float* qkv_w = (const float*)d_in[2];
    const float* qkv_b = (const float*)d_in[3];
    const float* out_w = (const float*)d_in[4];
    const float* out_b = (const float*)d_in[5];
    const float* w1    = (const float*)d_in[6];
    const float* w3    = (const float*)d_in[7];
    const float* w2    = (const float*)d_in[8];
    const float* n1g   = (const float*)d_in[9];
    const float* n1b   = (const float*)d_in[10];
    const float* n2g   = (const float*)d_in[11];
    const float* n2b   = (const float*)d_in[12];
    float* out = (float*)d_out;

    cudaFuncSetAttribute(mma_gemm_kernel, cudaFuncAttributeMaxDynamicSharedMemorySize, GEMM_SMEM);
    cudaFuncSetAttribute(attn_mma, cudaFuncAttributeMaxDynamicSharedMemorySize, ATTN_SMEM);

    void* p;
    cudaGetSymbolAddress(&p, g_attn);   float* attn   = (float*)p;
    cudaGetSymbolAddress(&p, g_h1);     float* h1     = (float*)p;
    cudaGetSymbolAddress(&p, g_qkv_h);  __half* qkvh  = (__half*)p;
    cudaGetSymbolAddress(&p, g_gateup); __half* gateup = (__half*)p;
    cudaGetSymbolAddress(&p, g_act_h);  __half* ah    = (__half*)p;
    cudaGetSymbolAddress(&p, g_wqkv);   __half* wq  = (__half*)p;
    cudaGetSymbolAddress(&p, g_wout);   __half* wo  = (__half*)p;
    cudaGetSymbolAddress(&p, g_w13);    __half* w13 = (__half*)p;
    cudaGetSymbolAddress(&p, g_w2);     __half* w2p = (__half*)p;
    cudaGetSymbolAddress(&p, g_q13);    __half* q13 = (__half*)p;
    cudaGetSymbolAddress(&p, g_kx);     __half* kx  = (__half*)p;
    cudaGetSymbolAddress(&p, g_kc);     __half* kc  = (__half*)p;

    dim3 tb(32, 8);
    build_rope_table<<<(MAXPOS * 32 + 255) / 256, 256>>>();

    // weight transpose + single fp16 (pre-scaled); w1,w3 packed [5632][1024]
    wt_f16_kernel<<<dim3(3 * DM / 32, DM / 32), tb>>>(qkv_w, wq, DM, 3 * DM);
    wt_f16_kernel<<<dim3(DM / 32, DM / 32),     tb>>>(out_w, wo, DM, DM);
    wt_f16_kernel<<<dim3(HID / 32, DM / 32),    tb>>>(w1, w13, DM, HID);
    wt_f16_kernel<<<dim3(HID / 32, DM / 32),    tb>>>(w3, w13 + (size_t)HID * DM, DM, HID);
    wt_f16_kernel<<<dim3(DM / 32, HID / 32),    tb>>>(w2, w2p, HID, DM);

    // LN1 -> fp16 A buffer [LTOT][DM]
    ln_f16_kernel<<<LXX, 256>>>(x,   ah,                    n1g, n1b);
    ln_f16_kernel<<<LCC, 256>>>(ctx, ah + (size_t)LXX * DM, n1g, n1b);

    // QKV projection (fp16 out, bias)
    mma_gemm_kernel<<<dim3(3 * DM / 128, LTOT / 128), 256, GEMM_SMEM>>>(
        ah, wq, nullptr, qkvh, qkv_b, nullptr, nullptr, 0, LTOT, 3 * DM, DM);

    // RoPE: qx -> q13 rows 0..2047, qs -> q13 rows 2048..4095 (both QSCALE);
    //       K paths scale 1.0; V stays in qkvh (strided)
    rope_f16_kernel<<<(LXX * 512 + 255) / 256, 256>>>(qkvh, 3 * DM, q13, LXX, POS_X, QSCALE);
    rope_f16_kernel<<<(2048 * 512 + 255) / 256, 256>>>(qkvh + (size_t)(LXX + HWSP) * 3 * DM, 3 * DM, q13 + (size_t)2048 * DM, 2048, HWSP, QSCALE);
    rope_f16_kernel<<<(LXX * 512 + 255) / 256, 256>>>(qkvh + DM, 3 * DM, kx, LXX, POS_X, 1.f);
    rope_f16_kernel<<<(LCC * 512 + 255) / 256, 256>>>(qkvh + (size_t)LXX * 3 * DM + DM, 3 * DM, kc, LCC, POS_C, 1.f);

    const __half* vx = qkvh + 2 * DM;                          // rows 0..2047 (strided)
    const __half* vc = qkvh + (size_t)LXX * 3 * DM + 2 * DM;   // rows 2048..6143 (strided)

    // merged a1|a3 (mode 3): q-tiles 0..15 -> fp32 attn ; 16..31 -> fp16 ah rows 2048+
    attn_mma<<<dim3(LOUT / 128, NH), 128, ATTN_SMEM>>>(q13, kc, vc, 3 * DM,
        attn, ah, LCC, 0, 3);
    // a2 (mode 1: +a1 from fp32 attn -> fp16 ah rows 0..2047)
    attn_mma<<<dim3(LXX / 128, NH), 128, ATTN_SMEM>>>(q13, kx, vx, 3 * DM,
        attn, ah, LXX, 1, 1);

    // out projection + bias + residual -> h1 (fp32)
    mma_gemm_kernel<<<dim3(DM / 128, LOUT / 128), 256, GEMM_SMEM>>>(
        ah, wo, h1, nullptr, out_b, x, ctx, 2048, LOUT, DM, DM);

    // LN2 -> fp16
    ln_f16_kernel<<<LOUT, 256>>>(h1, ah, n2g, n2b);

    // FFN: combined w1|w3 GEMM -> gateup (fp16), fused silu*mul -> fp16, w2 GEMM
    mma_gemm_kernel<<<dim3(2 * HID / 128, LOUT / 128), 256, GEMM_SMEM>>>(
        ah, w13, nullptr, gateup, nullptr, nullptr, nullptr, 0, LOUT, 2 * HID, DM);
    silu_mul_f16_kernel<<<dim3(HID / 256, LOUT), 256>>>(gateup, ah);
    mma_gemm_kernel<<<dim3(DM / 128, LOUT / 128), 256, GEMM_SMEM>>>(
        ah, w2p, out, nullptr, nullptr, h1, h1, LOUT, LOUT, DM, HID);
}